// round 7
// baseline (speedup 1.0000x reference)
#include <cuda_runtime.h>
#include <mma.h>
#include <math.h>
#include <cstdint>

using namespace nvcuda;

#define NBATCH 2
#define NT     2048
#define NDM    1024
#define NH     16
#define ND     64
#define QKVN   (NH * 5 * ND)   // 5120
#define BTOT   (NBATCH * NT)   // 4096

// Scratch (device-global; allocation-free per harness rules)
__device__ float g_qkv[(size_t)BTOT * QKVN];    // tf32-rounded, q-scaled
__device__ float g_attn[(size_t)BTOT * NDM];    // tf32-rounded
__device__ float g_x  [(size_t)BTOT * NDM];     // tf32-rounded x
__device__ float g_wq [(size_t)NDM * QKVN];     // tf32-rounded W_qkv
__device__ float g_wo [(size_t)NDM * NDM];      // tf32-rounded W_out

__device__ __forceinline__ float tf32r(float x) { return wmma::__float_to_tf32(x); }

__device__ __forceinline__ uint32_t smem_u32(const void* p) {
  uint32_t a;
  asm("{ .reg .u64 t; cvta.to.shared.u64 t, %1; cvt.u32.u64 %0, t; }"
      : "=r"(a) : "l"(p));
  return a;
}

#define CP_ASYNC16(dst, src) \
  asm volatile("cp.async.cg.shared.global [%0], [%1], 16;" :: "r"(dst), "l"(src))
#define CP_COMMIT() asm volatile("cp.async.commit_group;" ::: "memory")
#define CP_WAIT(n)  asm volatile("cp.async.wait_group %0;" :: "n"(n) : "memory")

// ---------------------------------------------------------------------------
// tf32 pre-round kernel
// ---------------------------------------------------------------------------
__global__ void round_tf32_kernel(const float* __restrict__ in,
                                  float* __restrict__ out, int n4) {
  int i = blockIdx.x * blockDim.x + threadIdx.x;
  if (i < n4) {
    float4 v = ((const float4*)in)[i];
    v.x = tf32r(v.x); v.y = tf32r(v.y); v.z = tf32r(v.z); v.w = tf32r(v.w);
    ((float4*)out)[i] = v;
  }
}

// ---------------------------------------------------------------------------
// TF32 wmma GEMM, cp.async 3-stage (R5-proven: 610us/150us, 2 CTA/SM).
// C[M,N] = A[M,K] @ B[K,N], row-major. Block 128x128x32, 8 warps 2x4.
// mode 0: plain fp32 store. mode 1: qkv epilogue (scale q cols, tf32-round).
// ---------------------------------------------------------------------------
#define TMM 128
#define TNN 128
#define TKK 32
#define LDA 36
#define LDB 132
#define A_STG (TMM * LDA)
#define B_STG (TKK * LDB)
#define GEMM_SMEM (3 * (A_STG + B_STG) * (int)sizeof(float))
#define LDS 132

__global__ __launch_bounds__(256, 2) void gemm_tc(
    const float* __restrict__ A, const float* __restrict__ B,
    float* __restrict__ C, int M, int N, int K, int mode) {
  extern __shared__ float smg[];
  float* Asm = smg;
  float* Bsm = smg + 3 * A_STG;
  const uint32_t sA = smem_u32(Asm);
  const uint32_t sB = smem_u32(Bsm);

  const int tid  = threadIdx.x;
  const int warp = tid >> 5;
  const int wm   = warp & 1;
  const int wn   = warp >> 1;
  const int bm   = blockIdx.y * TMM;
  const int bn   = blockIdx.x * TNN;

#define G_ISSUE(k0, s)                                                         \
  {                                                                            \
    uint32_t aB = sA + (uint32_t)(s) * (A_STG * 4);                            \
    uint32_t bB = sB + (uint32_t)(s) * (B_STG * 4);                            \
    _Pragma("unroll") for (int j = 0; j < 4; j++) {                            \
      int f = tid + j * 256;                                                   \
      int r = f >> 3, c4 = (f & 7) * 4;                                        \
      CP_ASYNC16(aB + (uint32_t)(r * LDA + c4) * 4,                            \
                 &A[(size_t)(bm + r) * K + (k0) + c4]);                        \
    }                                                                          \
    _Pragma("unroll") for (int j = 0; j < 4; j++) {                            \
      int f = tid + j * 256;                                                   \
      int r = f >> 5, c4 = (f & 31) * 4;                                       \
      CP_ASYNC16(bB + (uint32_t)(r * LDB + c4) * 4,                            \
                 &B[(size_t)((k0) + r) * N + bn + c4]);                        \
    }                                                                          \
    CP_COMMIT();                                                               \
  }

  wmma::fragment<wmma::accumulator, 16, 16, 8, float> acc[4][2];
#pragma unroll
  for (int i = 0; i < 4; i++)
#pragma unroll
    for (int j = 0; j < 2; j++) wmma::fill_fragment(acc[i][j], 0.0f);

  G_ISSUE(0, 0);
  G_ISSUE(TKK, 1);

  const int niter = K / TKK;
  for (int it = 0; it < niter; it++) {
    if (it == niter - 1) CP_WAIT(0); else CP_WAIT(1);
    __syncthreads();
    if (it + 2 < niter) G_ISSUE((it + 2) * TKK, (it + 2) % 3);

    const float* As_ = Asm + (it % 3) * A_STG;
    const float* Bs_ = Bsm + (it % 3) * B_STG;
#pragma unroll
    for (int kk = 0; kk < TKK; kk += 8) {
      wmma::fragment<wmma::matrix_a, 16, 16, 8, wmma::precision::tf32, wmma::row_major> af[4];
      wmma::fragment<wmma::matrix_b, 16, 16, 8, wmma::precision::tf32, wmma::row_major> bf[2];
#pragma unroll
      for (int i = 0; i < 4; i++)
        wmma::load_matrix_sync(af[i], &As_[(wm * 64 + i * 16) * LDA + kk], LDA);
#pragma unroll
      for (int j = 0; j < 2; j++)
        wmma::load_matrix_sync(bf[j], &Bs_[kk * LDB + wn * 32 + j * 16], LDB);
#pragma unroll
      for (int i = 0; i < 4; i++)
#pragma unroll
        for (int j = 0; j < 2; j++)
          wmma::mma_sync(acc[i][j], af[i], bf[j], acc[i][j]);
    }
  }

  __syncthreads();
#pragma unroll
  for (int i = 0; i < 4; i++)
#pragma unroll
    for (int j = 0; j < 2; j++)
      wmma::store_matrix_sync(&smg[(wm * 64 + i * 16) * LDS + wn * 32 + j * 16],
                              acc[i][j], LDS, wmma::mem_row_major);
  __syncthreads();

#pragma unroll
  for (int i = 0; i < 16; i++) {
    int f = tid + i * 256;
    int r = f >> 5, c4 = (f & 31) * 4;
    float4 v = *(const float4*)&smg[r * LDS + c4];
    if (mode == 1) {
      int gc = bn + c4;
      float s = ((gc % 320) < 128) ? 0.125f : 1.0f;
      v.x = tf32r(v.x * s); v.y = tf32r(v.y * s);
      v.z = tf32r(v.z * s); v.w = tf32r(v.w * s);
    }
    *(float4*)&C[(size_t)(bm + r) * N + bn + c4] = v;
  }
}

// ---------------------------------------------------------------------------
// Single-pass differential attention (R5 structure) with 3-stage KV ring:
// ONE __syncthreads per key-tile. Q frags register-resident; dual S buffers;
// single V fetch feeds both PV accumulations. 256 threads, 128-query tile.
// ---------------------------------------------------------------------------
#define ALD 68
#define KV_STG (3 * 64 * ALD)  // k1|k2|v per stage (52,224 B)

using FragAcc = wmma::fragment<wmma::accumulator, 16, 16, 8, float>;
using FragA   = wmma::fragment<wmma::matrix_a, 16, 16, 8, wmma::precision::tf32, wmma::row_major>;
using FragBc  = wmma::fragment<wmma::matrix_b, 16, 16, 8, wmma::precision::tf32, wmma::col_major>;
using FragBr  = wmma::fragment<wmma::matrix_b, 16, 16, 8, wmma::precision::tf32, wmma::row_major>;

#define ATTN_SMEM ((3 * KV_STG + 2 * 128 * ALD) * (int)sizeof(float))  // 226,304 B

__global__ __launch_bounds__(256) void attn_kernel(
    const float* __restrict__ lam_p, float* __restrict__ attn_out) {
  extern __shared__ float sm[];
  float* kvs = sm;                    // 3 x (k1|k2|v, each 64 x ALD)
  float* ss1 = kvs + 3 * KV_STG;      // 128 x ALD (Q1 staging -> S1/P1 -> O1)
  float* ss2 = ss1 + 128 * ALD;       // 128 x ALD (Q2 staging -> S2/P2 -> O2)
  const uint32_t sKV = smem_u32(kvs);
  const uint32_t sS1 = smem_u32(ss1);
  const uint32_t sS2 = smem_u32(ss2);

  const int tid  = threadIdx.x;
  const int warp = tid >> 5;
  const int wr   = warp * 16;
  const int b    = blockIdx.z;
  const int h    = blockIdx.y;
  const int i0   = (int)(gridDim.x - 1 - blockIdx.x) * 128;  // heavy first
  const float lamc = fminf(fmaxf(lam_p[h], 0.0f), 1.0f);

  const float* base = g_qkv + (size_t)b * NT * QKVN + h * (5 * ND);

#define ATT_ISSUE_KV(j0, bufi)                                                 \
  {                                                                            \
    uint32_t dstb = sKV + (uint32_t)(bufi) * (KV_STG * 4);                     \
    _Pragma("unroll") for (int i = 0; i < 12; i++) {                           \
      int f = tid + i * 256;                                                   \
      int mat = f >> 10, r = (f >> 4) & 63, c4 = (f & 15) * 4;                 \
      CP_ASYNC16(dstb + (uint32_t)(mat * 64 * ALD + r * ALD + c4) * 4,         \
                 &base[(size_t)((j0) + r) * QKVN + (2 + mat) * ND + c4]);      \
    }                                                                          \
    CP_COMMIT();                                                               \
  }

  // Prologue: G0 = Q1->ss1, Q2->ss2 ; G1 = KV0 ; G2 = KV1
  {
#pragma unroll
    for (int i = 0; i < 16; i++) {
      int f = tid + i * 256;
      int mat = f >> 11, r = (f >> 4) & 127, c4 = (f & 15) * 4;
      CP_ASYNC16((mat ? sS2 : sS1) + (uint32_t)(r * ALD + c4) * 4,
                 &base[(size_t)(i0 + r) * QKVN + mat * ND + c4]);
    }
    CP_COMMIT();
    ATT_ISSUE_KV(0, 0);
    ATT_ISSUE_KV(64, 1);
  }

  // Q fragments -> registers (frees ss1/ss2 for S use)
  FragA q1f[8], q2f[8];
  CP_WAIT(2);
  __syncthreads();
#pragma unroll
  for (int kk = 0; kk < 8; kk++) {
    wmma::load_matrix_sync(q1f[kk], &ss1[wr * ALD + kk * 8], ALD);
    wmma::load_matrix_sync(q2f[kk], &ss2[wr * ALD + kk * 8], ALD);
  }

  FragAcc O1[4], O2[4];
#pragma unroll
  for (int i = 0; i < 4; i++) {
    wmma::fill_fragment(O1[i], 0.0f);
    wmma::fill_fragment(O2[i], 0.0f);
  }
  float l1acc = 0.0f, l2acc = 0.0f;
  const int r_el = tid >> 1;
  const int cb   = (tid & 1) * 32;

  const int ntiles = i0 / 64 + 2;
  for (int t = 0; t < ntiles; t++) {
    const int j0 = t * 64;
    if (t == ntiles - 1) CP_WAIT(0); else CP_WAIT(1);
    __syncthreads();  // tile t visible to all; all warps past tile t-1
    // refill the buffer freed at tile t-1 (3-stage ring -> legal right now)
    if (t + 2 < ntiles) ATT_ISSUE_KV((t + 2) * 64, (t + 2) % 3);

    const float* kb1 = kvs + (t % 3) * KV_STG;
    const float* kb2 = kb1 + 64 * ALD;
    const float* vb_ = kb1 + 2 * 64 * ALD;

    // ---- S1, S2 strips ----
#pragma unroll
    for (int jt = 0; jt < 4; jt++) {
      FragAcc s1a, s2a;
      wmma::fill_fragment(s1a, 0.0f);
      wmma::fill_fragment(s2a, 0.0f);
#pragma unroll
      for (int kk = 0; kk < 8; kk++) {
        FragBc b1, b2;
        wmma::load_matrix_sync(b1, &kb1[(jt * 16) * ALD + kk * 8], ALD);
        wmma::load_matrix_sync(b2, &kb2[(jt * 16) * ALD + kk * 8], ALD);
        wmma::mma_sync(s1a, q1f[kk], b1, s1a);
        wmma::mma_sync(s2a, q2f[kk], b2, s2a);
      }
      wmma::store_matrix_sync(&ss1[wr * ALD + jt * 16], s1a, ALD, wmma::mem_row_major);
      wmma::store_matrix_sync(&ss2[wr * ALD + jt * 16], s2a, ALD, wmma::mem_row_major);
    }
    __syncwarp();

    // ---- exp + causal mask + row-sum partials (warp-local rows) ----
    {
      float* sr1 = &ss1[r_el * ALD + cb];
      float* sr2 = &ss2[r_el * ALD + cb];
      const int lim = i0 + r_el - j0 - cb;
      if (j0 + 63 > i0) {
#pragma unroll
        for (int c = 0; c < 32; c += 4) {
          float4 a4 = *(float4*)&sr1[c];
          float4 b4 = *(float4*)&sr2[c];
          float p0 = __expf(a4.x), p1 = __expf(a4.y), p2 = __expf(a4.z), p3 = __expf(a4.w);
          float u0 = __expf(b4.x), u1 = __expf(b4.y), u2 = __expf(b4.z), u3 = __expf(b4.w);
          if (c + 0 > lim) { p0 = 0.0f; u0 = 0.0f; }
          if (c + 1 > lim) { p1 = 0.0f; u1 = 0.0f; }
          if (c + 2 > lim) { p2 = 0.0f; u2 = 0.0f; }
          if (c + 3 > lim) { p3 = 0.0f; u3 = 0.0f; }
          l1acc += (p0 + p1) + (p2 + p3);
          l2acc += (u0 + u1) + (u2 + u3);
          a4.x = tf32r(p0); a4.y = tf32r(p1); a4.z = tf32r(p2); a4.w = tf32r(p3);
          b4.x = tf32r(u0); b4.y = tf32r(u1); b4.z = tf32r(u2); b4.w = tf32r(u3);
          *(float4*)&sr1[c] = a4;
          *(float4*)&sr2[c] = b4;
        }
      } else {
#pragma unroll
        for (int c = 0; c < 32; c += 4) {
          float4 a4 = *(float4*)&sr1[c];
          float4 b4 = *(float4*)&sr2[c];
          float p0 = __expf(a4.x), p1 = __expf(a4.y), p2 = __expf(a4.z), p3 = __expf(a4.w);
          float u0 = __expf(b4.x), u1 = __expf(b4.y), u2 = __expf(b4.z), u3 = __expf(b4.w);
          l1acc += (p0 + p1) + (p2 + p3);
          l2acc += (u0 + u1) + (u2 + u3);
          a4.x = tf32r(p0); a4.y = tf32r(p1); a4.z = tf32r(p2); a4.w = tf32r(p3);
          b4.x = tf32r(u0); b4.y = tf32r(u1); b4.z = tf32r(u2); b4.w = tf32r(u3);
          *(float4*)&sr1[c] = a4;
          *(float4*)&sr2[c] = b4;
        }
      }
    }
    __syncwarp();

    // ---- PV: single V fetch feeds both accumulations ----
#pragma unroll
    for (int kk = 0; kk < 8; kk++) {
      FragA pa1, pa2;
      wmma::load_matrix_sync(pa1, &ss1[wr * ALD + kk * 8], ALD);
      wmma::load_matrix_sync(pa2, &ss2[wr * ALD + kk * 8], ALD);
#pragma unroll
      for (int dt = 0; dt < 4; dt++) {
        FragBr vb;
        wmma::load_matrix_sync(vb, &vb_[(kk * 8) * ALD + dt * 16], ALD);
        wmma::mma_sync(O1[dt], pa1, vb, O1[dt]);
        wmma::mma_sync(O2[dt], pa2, vb, O2[dt]);
      }
    }
  }

  // Park O1/O2 in warp-private ss strips
#pragma unroll
  for (int dt = 0; dt < 4; dt++) {
    wmma::store_matrix_sync(&ss1[wr * ALD + dt * 16], O1[dt], ALD, wmma::mem_row_major);
    wmma::store_matrix_sync(&ss2[wr * ALD + dt * 16], O2[dt], ALD, wmma::mem_row_major);
  }
  __syncwarp();

  const float l1 = l1acc + __shfl_xor_sync(0xFFFFFFFFu, l1acc, 1);
  const float l2 = l2acc + __shfl_xor_sync(0xFFFFFFFFu, l2acc, 1);
  const float inv1 = 1.0f / l1;
  const float inv2 = lamc / l2;

  const float* o1r = &ss1[r_el * ALD + cb];
  const float* o2r = &ss2[r_el * ALD + cb];
  float* outp = attn_out + (size_t)(b * NT + i0 + r_el) * NDM + h * ND + cb;
#pragma unroll
  for (int c = 0; c < 32; c += 4) {
    float4 a = *(const float4*)&o1r[c];
    float4 d = *(const float4*)&o2r[c];
    float4 o;
    o.x = tf32r(a.x * inv1 - d.x * inv2);
    o.y = tf32r(a.y * inv1 - d.y * inv2);
    o.z = tf32r(a.z * inv1 - d.z * inv2);
    o.w = tf32r(a.w * inv1 - d.w * inv2);
    *(float4*)&outp[c] = o;
  }
}

// ---------------------------------------------------------------------------
extern "C" void kernel_launch(void* const* d_in, const int* in_sizes, int n_in,
                              void* d_out, int out_size) {
  const float* x    = (const float*)d_in[0];
  // d_in[1] = mask: exact causal additive mask; handled analytically.
  const float* Wqkv = (const float*)d_in[2];
  const float* Wout = (const float*)d_in[3];
  const float* lam  = (const float*)d_in[4];
  float* out = (float*)d_out;

  float *qkv_d, *attn_d, *x_d, *wq_d, *wo_d;
  cudaGetSymbolAddress((void**)&qkv_d, g_qkv);
  cudaGetSymbolAddress((void**)&attn_d, g_attn);
  cudaGetSymbolAddress((void**)&x_d, g_x);
  cudaGetSymbolAddress((void**)&wq_d, g_wq);
  cudaGetSymbolAddress((void**)&wo_d, g_wo);

  cudaFuncSetAttribute(gemm_tc, cudaFuncAttributeMaxDynamicSharedMemorySize, GEMM_SMEM);
  cudaFuncSetAttribute(attn_kernel, cudaFuncAttributeMaxDynamicSharedMemorySize, ATTN_SMEM);

  // 0) pre-round inputs to tf32
  {
    int n4x = BTOT * NDM / 4;
    round_tf32_kernel<<<n4x / 256, 256>>>(x, x_d, n4x);
    int n4q = NDM * QKVN / 4;
    round_tf32_kernel<<<n4q / 256, 256>>>(Wqkv, wq_d, n4q);
    int n4o = NDM * NDM / 4;
    round_tf32_kernel<<<n4o / 256, 256>>>(Wout, wo_d, n4o);
  }

  // 1) qkv = x @ W_qkv  (epilogue: scale q cols + tf32 round)
  {
    dim3 grid(QKVN / TNN, BTOT / TMM);  // (40, 32)
    gemm_tc<<<grid, 256, GEMM_SMEM>>>(x_d, wq_d, qkv_d, BTOT, QKVN, NDM, 1);
  }

  // 2) differential attention (3-stage KV ring, 1 barrier/tile)
  {
    dim3 grid(NT / 128, NH, NBATCH);  // (16, 16, 2)
    attn_kernel<<<grid, 256, ATTN_SMEM>>>(lam, attn_d);
  }

  // 3) out = attn @ W_out
  {
    dim3 grid(NDM / TNN, BTOT / TMM);  // (8, 32)
    gemm_tc<<<grid, 256, GEMM_SMEM>>>(attn_d, wo_d, out, BTOT, NDM, NDM, 0);
  }
}

// round 8
// speedup vs baseline: 1.4876x; 1.4876x over previous
#include <cuda_runtime.h>
#include <mma.h>
#include <math.h>
#include <cstdint>

using namespace nvcuda;

#define NBATCH 2
#define NT     2048
#define NDM    1024
#define NH     16
#define ND     64
#define QKVN   (NH * 5 * ND)   // 5120
#define BTOT   (NBATCH * NT)   // 4096

// Scratch (device-global; allocation-free per harness rules)
__device__ float g_qkv[(size_t)BTOT * QKVN];    // row-major, tf32-rounded, q-scaled
__device__ float g_attn[(size_t)BTOT * NDM];    // PACKED A-frag layout, tf32-rounded
__device__ float g_x  [(size_t)BTOT * NDM];     // PACKED A-frag layout
__device__ float g_wq [(size_t)NDM * QKVN];     // PACKED B-frag layout
__device__ float g_wo [(size_t)NDM * NDM];      // PACKED B-frag layout

__device__ __forceinline__ float tf32r(float x) { return wmma::__float_to_tf32(x); }

__device__ __forceinline__ uint32_t smem_u32(const void* p) {
  uint32_t a;
  asm("{ .reg .u64 t; cvta.to.shared.u64 t, %1; cvt.u32.u64 %0, t; }"
      : "=r"(a) : "l"(p));
  return a;
}

#define CP_ASYNC16(dst, src) \
  asm volatile("cp.async.cg.shared.global [%0], [%1], 16;" :: "r"(dst), "l"(src))
#define CP_COMMIT() asm volatile("cp.async.commit_group;" ::: "memory")
#define CP_WAIT(n)  asm volatile("cp.async.wait_group %0;" :: "n"(n) : "memory")

__device__ __forceinline__ void mma_tf32(float4& d, const uint4& a, const uint2& b) {
  asm volatile(
      "mma.sync.aligned.m16n8k8.row.col.f32.tf32.tf32.f32 "
      "{%0,%1,%2,%3}, {%4,%5,%6,%7}, {%8,%9}, {%0,%1,%2,%3};\n"
      : "+f"(d.x), "+f"(d.y), "+f"(d.z), "+f"(d.w)
      : "r"(a.x), "r"(a.y), "r"(a.z), "r"(a.w), "r"(b.x), "r"(b.y));
}

// ---------------------------------------------------------------------------
// Packed layouts.
// A [M,K] -> [mb][kb][mi(8)][ki(4)][lane(32)][reg(4)] : frag m16k8,
//   a0=(g,t) a1=(g+8,t) a2=(g,t+4) a3=(g+8,t+4), lane = g*4+t.
// B [K,N] -> [kb][nb][ki(4)][ni(16)][lane(32)][reg(2)] : frag k8n8,
//   b0=(t,g) b1=(t+4,g).
// ---------------------------------------------------------------------------
__global__ void permute_A_kernel(const float* __restrict__ src,
                                 float* __restrict__ dst, int M, int K) {
  int idx = blockIdx.x * blockDim.x + threadIdx.x;  // one frag-lane (4 floats)
  int l  = idx & 31;
  int fi = (idx >> 5) & 31;
  int blk = idx >> 10;
  int Kb = K >> 5;
  int kb = blk % Kb, mb = blk / Kb;
  if (mb >= (M >> 7)) return;
  int mi = fi >> 2, ki = fi & 3;
  int g = l >> 2, t = l & 3;
  size_t r = mb * 128 + mi * 16 + g;
  size_t c = kb * 32 + ki * 8 + t;
  float4 v;
  v.x = tf32r(src[r * K + c]);
  v.y = tf32r(src[(r + 8) * K + c]);
  v.z = tf32r(src[r * K + c + 4]);
  v.w = tf32r(src[(r + 8) * K + c + 4]);
  ((float4*)dst)[idx] = v;
}

__global__ void permute_B_kernel(const float* __restrict__ src,
                                 float* __restrict__ dst, int K, int N) {
  int idx = blockIdx.x * blockDim.x + threadIdx.x;  // one frag-lane (2 floats)
  int l  = idx & 31;
  int fi = (idx >> 5) & 63;
  int blk = idx >> 11;
  int Nb = N >> 7;
  int nb = blk % Nb, kb = blk / Nb;
  if (kb >= (K >> 5)) return;
  int ki = fi >> 4, ni = fi & 15;
  int g = l >> 2, t = l & 3;
  size_t k = kb * 32 + ki * 8 + t;
  size_t n = nb * 128 + ni * 8 + g;
  float2 v;
  v.x = tf32r(src[k * N + n]);
  v.y = tf32r(src[(k + 4) * N + n]);
  ((float2*)dst)[idx] = v;
}

// ---------------------------------------------------------------------------
// Hand-mma TF32 GEMM: C[M,N] = A_packed @ B_packed, 128x128x32 block,
// 8 warps 2x4 (warp 64x32), cp.async 3-stage, 2 CTA/SM.
// mode 0: plain fp32 row-major store. mode 1: qkv epilogue (scale+round).
// ---------------------------------------------------------------------------
#define TMM 128
#define TNN 128
#define TKK 32
#define TILEF 4096                      // floats per packed 16KB tile
#define GEMM_SMEM (3 * 2 * TILEF * (int)sizeof(float))  // 98,304 B
#define LDS 132

__global__ __launch_bounds__(256, 2) void gemm_tc(
    const float* __restrict__ Apk, const float* __restrict__ Bpk,
    float* __restrict__ C, int M, int N, int K, int mode) {
  extern __shared__ float smg[];
  float* Asm = smg;
  float* Bsm = smg + 3 * TILEF;
  const uint32_t sA = smem_u32(Asm);
  const uint32_t sB = smem_u32(Bsm);

  const int tid  = threadIdx.x;
  const int lane = tid & 31;
  const int warp = tid >> 5;
  const int wm   = warp & 1;
  const int wn   = warp >> 1;
  const int bm   = blockIdx.y * TMM;
  const int bn   = blockIdx.x * TNN;
  const int Kb   = K >> 5;
  const int Nb   = N >> 7;

#define G_ISSUE(k0, s)                                                         \
  {                                                                            \
    const float* asrc = Apk + ((size_t)(bm >> 7) * Kb + ((k0) >> 5)) * TILEF;  \
    const float* bsrc = Bpk + ((size_t)((k0) >> 5) * Nb + (bn >> 7)) * TILEF;  \
    uint32_t aB = sA + (uint32_t)(s) * (TILEF * 4);                            \
    uint32_t bB = sB + (uint32_t)(s) * (TILEF * 4);                            \
    _Pragma("unroll") for (int j = 0; j < 4; j++)                              \
      CP_ASYNC16(aB + (uint32_t)(tid * 16 + j * 4096), asrc + tid * 4 + j * 1024); \
    _Pragma("unroll") for (int j = 0; j < 4; j++)                              \
      CP_ASYNC16(bB + (uint32_t)(tid * 16 + j * 4096), bsrc + tid * 4 + j * 1024); \
    CP_COMMIT();                                                               \
  }

  float4 acc[4][4];
#pragma unroll
  for (int i = 0; i < 4; i++)
#pragma unroll
    for (int j = 0; j < 4; j++) acc[i][j] = make_float4(0.f, 0.f, 0.f, 0.f);

  G_ISSUE(0, 0);
  G_ISSUE(TKK, 1);

  const int niter = K / TKK;
  for (int it = 0; it < niter; it++) {
    if (it == niter - 1) CP_WAIT(0); else CP_WAIT(1);
    __syncthreads();
    if (it + 2 < niter) G_ISSUE((it + 2) * TKK, (it + 2) % 3);

    const float* As_ = Asm + (it % 3) * TILEF;
    const float* Bs_ = Bsm + (it % 3) * TILEF;
#pragma unroll
    for (int ki = 0; ki < 4; ki++) {
      uint4 a[4];
      uint2 b[4];
#pragma unroll
      for (int i = 0; i < 4; i++)
        a[i] = *(const uint4*)&As_[(((wm * 4 + i) * 4 + ki) * 32 + lane) * 4];
#pragma unroll
      for (int j = 0; j < 4; j++)
        b[j] = *(const uint2*)&Bs_[((ki * 16 + wn * 4 + j) * 32 + lane) * 2];
#pragma unroll
      for (int i = 0; i < 4; i++)
#pragma unroll
        for (int j = 0; j < 4; j++) mma_tf32(acc[i][j], a[i], b[j]);
    }
  }

  // epilogue: stage in smem, then coalesced global write
  __syncthreads();
  {
    const int g = lane >> 2, t = lane & 3;
#pragma unroll
    for (int i = 0; i < 4; i++)
#pragma unroll
      for (int j = 0; j < 4; j++) {
        int r0 = wm * 64 + i * 16 + g;
        int cc = wn * 32 + j * 8 + t * 2;
        *(float2*)&smg[r0 * LDS + cc] = make_float2(acc[i][j].x, acc[i][j].y);
        *(float2*)&smg[(r0 + 8) * LDS + cc] = make_float2(acc[i][j].z, acc[i][j].w);
      }
  }
  __syncthreads();

#pragma unroll
  for (int i = 0; i < 16; i++) {
    int f = tid + i * 256;
    int r = f >> 5, c4 = (f & 31) * 4;
    float4 v = *(const float4*)&smg[r * LDS + c4];
    if (mode == 1) {
      int gc = bn + c4;
      float s = ((gc % 320) < 128) ? 0.125f : 1.0f;
      v.x = tf32r(v.x * s); v.y = tf32r(v.y * s);
      v.z = tf32r(v.z * s); v.w = tf32r(v.w * s);
    }
    *(float4*)&C[(size_t)(bm + r) * N + bn + c4] = v;
  }
}

// ---------------------------------------------------------------------------
// Single-pass differential attention (R5-proven shape, 2-stage KV).
// Epilogue writes g_attn in PACKED A-frag layout for the out-proj GEMM.
// ---------------------------------------------------------------------------
#define ALD 68
#define KV_STG (3 * 64 * ALD)

using FragAcc = wmma::fragment<wmma::accumulator, 16, 16, 8, float>;
using FragA   = wmma::fragment<wmma::matrix_a, 16, 16, 8, wmma::precision::tf32, wmma::row_major>;
using FragBc  = wmma::fragment<wmma::matrix_b, 16, 16, 8, wmma::precision::tf32, wmma::col_major>;
using FragBr  = wmma::fragment<wmma::matrix_b, 16, 16, 8, wmma::precision::tf32, wmma::row_major>;

#define ATTN_SMEM ((2 * KV_STG + 2 * 128 * ALD) * (int)sizeof(float))  // 174,080 B

__global__ __launch_bounds__(256) void attn_kernel(
    const float* __restrict__ lam_p, float* __restrict__ attn_out) {
  extern __shared__ float sm[];
  float* kvs = sm;                    // 2 x (k1|k2|v, each 64 x ALD)
  float* ss1 = kvs + 2 * KV_STG;      // 128 x ALD
  float* ss2 = ss1 + 128 * ALD;       // 128 x ALD
  const uint32_t sKV = smem_u32(kvs);
  const uint32_t sS1 = smem_u32(ss1);
  const uint32_t sS2 = smem_u32(ss2);

  const int tid  = threadIdx.x;
  const int warp = tid >> 5;
  const int wr   = warp * 16;
  const int b    = blockIdx.z;
  const int h    = blockIdx.y;
  const int i0   = (int)(gridDim.x - 1 - blockIdx.x) * 128;  // heavy first
  const float lamc = fminf(fmaxf(lam_p[h], 0.0f), 1.0f);

  const float* base = g_qkv + (size_t)b * NT * QKVN + h * (5 * ND);

#define ATT_ISSUE_KV(j0, bufi)                                                 \
  {                                                                            \
    uint32_t dstb = sKV + (uint32_t)(bufi) * (KV_STG * 4);                     \
    _Pragma("unroll") for (int i = 0; i < 12; i++) {                           \
      int f = tid + i * 256;                                                   \
      int mat = f >> 10, r = (f >> 4) & 63, c4 = (f & 15) * 4;                 \
      CP_ASYNC16(dstb + (uint32_t)(mat * 64 * ALD + r * ALD + c4) * 4,         \
                 &base[(size_t)((j0) + r) * QKVN + (2 + mat) * ND + c4]);      \
    }                                                                          \
    CP_COMMIT();                                                               \
  }

  // Prologue: G0 = Q1->ss1, Q2->ss2 ; G1 = KV0 ; G2 = KV1
  {
#pragma unroll
    for (int i = 0; i < 16; i++) {
      int f = tid + i * 256;
      int mat = f >> 11, r = (f >> 4) & 127, c4 = (f & 15) * 4;
      CP_ASYNC16((mat ? sS2 : sS1) + (uint32_t)(r * ALD + c4) * 4,
                 &base[(size_t)(i0 + r) * QKVN + mat * ND + c4]);
    }
    CP_COMMIT();
    ATT_ISSUE_KV(0, 0);
    ATT_ISSUE_KV(64, 1);
  }

  FragA q1f[8], q2f[8];
  CP_WAIT(2);
  __syncthreads();
#pragma unroll
  for (int kk = 0; kk < 8; kk++) {
    wmma::load_matrix_sync(q1f[kk], &ss1[wr * ALD + kk * 8], ALD);
    wmma::load_matrix_sync(q2f[kk], &ss2[wr * ALD + kk * 8], ALD);
  }

  FragAcc O1[4], O2[4];
#pragma unroll
  for (int i = 0; i < 4; i++) {
    wmma::fill_fragment(O1[i], 0.0f);
    wmma::fill_fragment(O2[i], 0.0f);
  }
  float l1acc = 0.0f, l2acc = 0.0f;
  const int r_el = tid >> 1;
  const int cb   = (tid & 1) * 32;

  const int ntiles = i0 / 64 + 2;
  for (int t = 0; t < ntiles; t++) {
    const int j0 = t * 64;
    if (t == ntiles - 1) CP_WAIT(0); else CP_WAIT(1);
    __syncthreads();

    const float* kb1 = kvs + (t & 1) * KV_STG;
    const float* kb2 = kb1 + 64 * ALD;
    const float* vb_ = kb1 + 2 * 64 * ALD;

#pragma unroll
    for (int jt = 0; jt < 4; jt++) {
      FragAcc s1a, s2a;
      wmma::fill_fragment(s1a, 0.0f);
      wmma::fill_fragment(s2a, 0.0f);
#pragma unroll
      for (int kk = 0; kk < 8; kk++) {
        FragBc b1, b2;
        wmma::load_matrix_sync(b1, &kb1[(jt * 16) * ALD + kk * 8], ALD);
        wmma::load_matrix_sync(b2, &kb2[(jt * 16) * ALD + kk * 8], ALD);
        wmma::mma_sync(s1a, q1f[kk], b1, s1a);
        wmma::mma_sync(s2a, q2f[kk], b2, s2a);
      }
      wmma::store_matrix_sync(&ss1[wr * ALD + jt * 16], s1a, ALD, wmma::mem_row_major);
      wmma::store_matrix_sync(&ss2[wr * ALD + jt * 16], s2a, ALD, wmma::mem_row_major);
    }
    __syncwarp();

    {
      float* sr1 = &ss1[r_el * ALD + cb];
      float* sr2 = &ss2[r_el * ALD + cb];
      const int lim = i0 + r_el - j0 - cb;
      if (j0 + 63 > i0) {
#pragma unroll
        for (int c = 0; c < 32; c += 4) {
          float4 a4 = *(float4*)&sr1[c];
          float4 b4 = *(float4*)&sr2[c];
          float p0 = __expf(a4.x), p1 = __expf(a4.y), p2 = __expf(a4.z), p3 = __expf(a4.w);
          float u0 = __expf(b4.x), u1 = __expf(b4.y), u2 = __expf(b4.z), u3 = __expf(b4.w);
          if (c + 0 > lim) { p0 = 0.0f; u0 = 0.0f; }
          if (c + 1 > lim) { p1 = 0.0f; u1 = 0.0f; }
          if (c + 2 > lim) { p2 = 0.0f; u2 = 0.0f; }
          if (c + 3 > lim) { p3 = 0.0f; u3 = 0.0f; }
          l1acc += (p0 + p1) + (p2 + p3);
          l2acc += (u0 + u1) + (u2 + u3);
          a4.x = tf32r(p0); a4.y = tf32r(p1); a4.z = tf32r(p2); a4.w = tf32r(p3);
          b4.x = tf32r(u0); b4.y = tf32r(u1); b4.z = tf32r(u2); b4.w = tf32r(u3);
          *(float4*)&sr1[c] = a4;
          *(float4*)&sr2[c] = b4;
        }
      } else {
#pragma unroll
        for (int c = 0; c < 32; c += 4) {
          float4 a4 = *(float4*)&sr1[c];
          float4 b4 = *(float4*)&sr2[c];
          float p0 = __expf(a4.x), p1 = __expf(a4.y), p2 = __expf(a4.z), p3 = __expf(a4.w);
          float u0 = __expf(b4.x), u1 = __expf(b4.y), u2 = __expf(b4.z), u3 = __expf(b4.w);
          l1acc += (p0 + p1) + (p2 + p3);
          l2acc += (u0 + u1) + (u2 + u3);
          a4.x = tf32r(p0); a4.y = tf32r(p1); a4.z = tf32r(p2); a4.w = tf32r(p3);
          b4.x = tf32r(u0); b4.y = tf32r(u1); b4.z = tf32r(u2); b4.w = tf32r(u3);
          *(float4*)&sr1[c] = a4;
          *(float4*)&sr2[c] = b4;
        }
      }
    }
    __syncwarp();

#pragma unroll
    for (int kk = 0; kk < 8; kk++) {
      FragA pa1, pa2;
      wmma::load_matrix_sync(pa1, &ss1[wr * ALD + kk * 8], ALD);
      wmma::load_matrix_sync(pa2, &ss2[wr * ALD + kk * 8], ALD);
#pragma unroll
      for (int dt = 0; dt < 4; dt++) {
        FragBr vb;
        wmma::load_matrix_sync(vb, &vb_[(kk * 8) * ALD + dt * 16], ALD);
        wmma::mma_sync(O1[dt], pa1, vb, O1[dt]);
        wmma::mma_sync(O2[dt], pa2, vb, O2[dt]);
      }
    }
    __syncthreads();
    if (t + 2 < ntiles) ATT_ISSUE_KV((t + 2) * 64, t & 1);
  }

  // Park O1/O2 in warp-private ss strips
#pragma unroll
  for (int dt = 0; dt < 4; dt++) {
    wmma::store_matrix_sync(&ss1[wr * ALD + dt * 16], O1[dt], ALD, wmma::mem_row_major);
    wmma::store_matrix_sync(&ss2[wr * ALD + dt * 16], O2[dt], ALD, wmma::mem_row_major);
  }
  __syncwarp();

  const float l1 = l1acc + __shfl_xor_sync(0xFFFFFFFFu, l1acc, 1);
  const float l2 = l2acc + __shfl_xor_sync(0xFFFFFFFFu, l2acc, 1);
  const float inv1 = 1.0f / l1;
  const float inv2 = lamc / l2;

  // Packed-A write into g_attn: [mb][kb(32)][mi][ki][lane][reg]
  const float* o1r = &ss1[r_el * ALD + cb];
  const float* o2r = &ss2[r_el * ALD + cb];
  {
    const int grow = b * NT + i0 + r_el;
    const int mb = grow >> 7;
    const int mi = r_el >> 4;
    const int gg = r_el & 7;
    const int rowhalf = (r_el >> 3) & 1;
    const int kb = (h * 64 + cb) >> 5;
    float* dstb = attn_out +
        (((size_t)(mb * 32 + kb) * 32 + mi * 4) * 32 + gg * 4) * 4;
#pragma unroll
    for (int c = 0; c < 32; c++) {
      int ki = c >> 3, t = c & 3, colhalf = (c >> 2) & 1;
      float o = tf32r(o1r[c] * inv1 - o2r[c] * inv2);
      dstb[(size_t)(ki * 32 + t) * 4 + rowhalf + 2 * colhalf] = o;
    }
  }
}

// ---------------------------------------------------------------------------
extern "C" void kernel_launch(void* const* d_in, const int* in_sizes, int n_in,
                              void* d_out, int out_size) {
  const float* x    = (const float*)d_in[0];
  // d_in[1] = mask: exact causal additive mask; handled analytically.
  const float* Wqkv = (const float*)d_in[2];
  const float* Wout = (const float*)d_in[3];
  const float* lam  = (const float*)d_in[4];
  float* out = (float*)d_out;

  float *qkv_d, *attn_d, *x_d, *wq_d, *wo_d;
  cudaGetSymbolAddress((void**)&qkv_d, g_qkv);
  cudaGetSymbolAddress((void**)&attn_d, g_attn);
  cudaGetSymbolAddress((void**)&x_d, g_x);
  cudaGetSymbolAddress((void**)&wq_d, g_wq);
  cudaGetSymbolAddress((void**)&wo_d, g_wo);

  cudaFuncSetAttribute(gemm_tc, cudaFuncAttributeMaxDynamicSharedMemorySize, GEMM_SMEM);
  cudaFuncSetAttribute(attn_kernel, cudaFuncAttributeMaxDynamicSharedMemorySize, ATTN_SMEM);

  // 0) permute + tf32-round inputs into fragment-packed layouts
  permute_A_kernel<<<(BTOT / 128) * (NDM / 32) * 1024 / 256, 256>>>(x, x_d, BTOT, NDM);
  permute_B_kernel<<<(NDM / 32) * (QKVN / 128) * 2048 / 256, 256>>>(Wqkv, wq_d, NDM, QKVN);
  permute_B_kernel<<<(NDM / 32) * (NDM / 128) * 2048 / 256, 256>>>(Wout, wo_d, NDM, NDM);

  // 1) qkv = x @ W_qkv  (epilogue: scale q cols + tf32 round; row-major out)
  {
    dim3 grid(QKVN / TNN, BTOT / TMM);  // (40, 32)
    gemm_tc<<<grid, 256, GEMM_SMEM>>>(x_d, wq_d, qkv_d, BTOT, QKVN, NDM, 1);
  }

  // 2) differential attention (writes g_attn packed for out-proj)
  {
    dim3 grid(NT / 128, NH, NBATCH);  // (16, 16, 2)
    attn_kernel<<<grid, 256, ATTN_SMEM>>>(lam, attn_d);
  }

  // 3) out = attn @ W_out
  {
    dim3 grid(NDM / TNN, BTOT / TMM);  // (8, 32)
    gemm_tc<<<grid, 256, GEMM_SMEM>>>(attn_d, wo_d, out, BTOT, NDM, NDM, 0);
  }
}

// round 9
// speedup vs baseline: 2.3509x; 1.5803x over previous
#include <cuda_runtime.h>
#include <mma.h>
#include <math.h>
#include <cstdint>

using namespace nvcuda;

#define NBATCH 2
#define NT     2048
#define NDM    1024
#define NH     16
#define ND     64
#define QKVN   (NH * 5 * ND)   // 5120
#define BTOT   (NBATCH * NT)   // 4096

// Scratch (device-global; allocation-free per harness rules)
__device__ float g_qkv[(size_t)BTOT * QKVN];    // row-major, tf32-rounded, q-scaled
__device__ float g_attn[(size_t)BTOT * NDM];    // PACKED A-frag layout
__device__ float g_x  [(size_t)BTOT * NDM];     // PACKED A-frag layout
__device__ float g_wq [(size_t)NDM * QKVN];     // PACKED B-frag layout
__device__ float g_wo [(size_t)NDM * NDM];      // PACKED B-frag layout
__device__ float g_kvp[(size_t)NBATCH * NH * 32 * 12288];  // packed K1|K2|V per 64-key tile

__device__ __forceinline__ float tf32r(float x) { return wmma::__float_to_tf32(x); }

__device__ __forceinline__ uint32_t smem_u32(const void* p) {
  uint32_t a;
  asm("{ .reg .u64 t; cvta.to.shared.u64 t, %1; cvt.u32.u64 %0, t; }"
      : "=r"(a) : "l"(p));
  return a;
}

#define CP_ASYNC16(dst, src) \
  asm volatile("cp.async.cg.shared.global [%0], [%1], 16;" :: "r"(dst), "l"(src))
#define CP_COMMIT() asm volatile("cp.async.commit_group;" ::: "memory")
#define CP_WAIT(n)  asm volatile("cp.async.wait_group %0;" :: "n"(n) : "memory")

__device__ __forceinline__ void mma_tf32(float4& d, const uint4& a, const uint2& b) {
  asm volatile(
      "mma.sync.aligned.m16n8k8.row.col.f32.tf32.tf32.f32 "
      "{%0,%1,%2,%3}, {%4,%5,%6,%7}, {%8,%9}, {%0,%1,%2,%3};\n"
      : "+f"(d.x), "+f"(d.y), "+f"(d.z), "+f"(d.w)
      : "r"(a.x), "r"(a.y), "r"(a.z), "r"(a.w), "r"(b.x), "r"(b.y));
}

// Convert m16n8 accumulator layout -> m16k8 A-operand layout (quad shuffle).
// acc: c0=(g,2t) c1=(g,2t+1) c2=(g+8,2t) c3=(g+8,2t+1); A: a0=(g,t) a1=(g+8,t)
// a2=(g,t+4) a3=(g+8,t+4). Col c lives in src lane (c>>1), reg (c&1).
__device__ __forceinline__ float4 cvt_c2a(float4 c, int lane) {
  int tA = (lane & ~3) | ((lane & 3) >> 1);
  int tB = tA + 2;
  float e0 = __shfl_sync(0xffffffffu, c.x, tA);
  float e1 = __shfl_sync(0xffffffffu, c.y, tA);
  float e2 = __shfl_sync(0xffffffffu, c.z, tA);
  float e3 = __shfl_sync(0xffffffffu, c.w, tA);
  float f0 = __shfl_sync(0xffffffffu, c.x, tB);
  float f1 = __shfl_sync(0xffffffffu, c.y, tB);
  float f2 = __shfl_sync(0xffffffffu, c.z, tB);
  float f3 = __shfl_sync(0xffffffffu, c.w, tB);
  bool odd = lane & 1;
  float4 a;
  a.x = odd ? e1 : e0;
  a.y = odd ? e3 : e2;
  a.z = odd ? f1 : f0;
  a.w = odd ? f3 : f2;
  return a;
}

// ---------------------------------------------------------------------------
// Packed layouts (validated in R8).
// ---------------------------------------------------------------------------
__global__ void permute_A_kernel(const float* __restrict__ src,
                                 float* __restrict__ dst, int M, int K) {
  int idx = blockIdx.x * blockDim.x + threadIdx.x;
  int l  = idx & 31;
  int fi = (idx >> 5) & 31;
  int blk = idx >> 10;
  int Kb = K >> 5;
  int kb = blk % Kb, mb = blk / Kb;
  if (mb >= (M >> 7)) return;
  int mi = fi >> 2, ki = fi & 3;
  int g = l >> 2, t = l & 3;
  size_t r = mb * 128 + mi * 16 + g;
  size_t c = kb * 32 + ki * 8 + t;
  float4 v;
  v.x = tf32r(src[r * K + c]);
  v.y = tf32r(src[(r + 8) * K + c]);
  v.z = tf32r(src[r * K + c + 4]);
  v.w = tf32r(src[(r + 8) * K + c + 4]);
  ((float4*)dst)[idx] = v;
}

__global__ void permute_B_kernel(const float* __restrict__ src,
                                 float* __restrict__ dst, int K, int N) {
  int idx = blockIdx.x * blockDim.x + threadIdx.x;
  int l  = idx & 31;
  int fi = (idx >> 5) & 63;
  int blk = idx >> 11;
  int Nb = N >> 7;
  int nb = blk % Nb, kb = blk / Nb;
  if (kb >= (K >> 5)) return;
  int ki = fi >> 4, ni = fi & 15;
  int g = l >> 2, t = l & 3;
  size_t k = kb * 32 + ki * 8 + t;
  size_t n = nb * 128 + ni * 8 + g;
  float2 v;
  v.x = tf32r(src[k * N + n]);
  v.y = tf32r(src[(k + 4) * N + n]);
  ((float2*)dst)[idx] = v;
}

// KV pack: per (b,h,64-key tile): K1 frags [nb][kk] (b0=K[nb8+g][kk8+t],
// b1=+4 col), K2 same, V frags [kk][db] (b0=V[kk8+t][db8+g], b1=+4 row).
// Tile = 12288 floats (K1 4096 | K2 4096 | V 4096).
__global__ void permute_KV_kernel(const float* __restrict__ qkv,
                                  float* __restrict__ dst) {
  int idx = blockIdx.x * blockDim.x + threadIdx.x;  // 0..6143: frag-lane
  int lane = idx & 31;
  int frag = idx >> 5;         // 0..191
  int tile = blockIdx.y;       // (b*16+h)*32 + jb
  int b  = tile >> 9;
  int h  = (tile >> 5) & 15;
  int jb = tile & 31;
  int mat = frag >> 6;         // 0=K1 1=K2 2=V
  int f   = frag & 63;
  int g = lane >> 2, t = lane & 3;
  float2 v;
  if (mat < 2) {
    int nb = f >> 3, kk = f & 7;
    size_t row = (size_t)(b * NT + jb * 64 + nb * 8 + g);
    size_t col = (size_t)h * 320 + 128 + mat * 64 + kk * 8 + t;
    const float* p = qkv + row * QKVN + col;
    v.x = p[0];
    v.y = p[4];
  } else {
    int kk = f >> 3, db = f & 7;
    size_t row = (size_t)(b * NT + jb * 64 + kk * 8 + t);
    size_t col = (size_t)h * 320 + 256 + db * 8 + g;
    v.x = qkv[row * QKVN + col];
    v.y = qkv[(row + 4) * QKVN + col];
  }
  ((float2*)dst)[(size_t)tile * 6144 + frag * 32 + lane] = v;
}

// ---------------------------------------------------------------------------
// Hand-mma TF32 GEMM (R8-proven: 221us QKV). 128x128x32, 3-stage, 2 CTA/SM.
// ---------------------------------------------------------------------------
#define TMM 128
#define TNN 128
#define TKK 32
#define TILEF 4096
#define GEMM_SMEM (3 * 2 * TILEF * (int)sizeof(float))
#define LDS 132

__global__ __launch_bounds__(256, 2) void gemm_tc(
    const float* __restrict__ Apk, const float* __restrict__ Bpk,
    float* __restrict__ C, int M, int N, int K, int mode) {
  extern __shared__ float smg[];
  float* Asm = smg;
  float* Bsm = smg + 3 * TILEF;
  const uint32_t sA = smem_u32(Asm);
  const uint32_t sB = smem_u32(Bsm);

  const int tid  = threadIdx.x;
  const int lane = tid & 31;
  const int warp = tid >> 5;
  const int wm   = warp & 1;
  const int wn   = warp >> 1;
  const int bm   = blockIdx.y * TMM;
  const int bn   = blockIdx.x * TNN;
  const int Kb   = K >> 5;
  const int Nb   = N >> 7;

#define G_ISSUE(k0, s)                                                         \
  {                                                                            \
    const float* asrc = Apk + ((size_t)(bm >> 7) * Kb + ((k0) >> 5)) * TILEF;  \
    const float* bsrc = Bpk + ((size_t)((k0) >> 5) * Nb + (bn >> 7)) * TILEF;  \
    uint32_t aB = sA + (uint32_t)(s) * (TILEF * 4);                            \
    uint32_t bB = sB + (uint32_t)(s) * (TILEF * 4);                            \
    _Pragma("unroll") for (int j = 0; j < 4; j++)                              \
      CP_ASYNC16(aB + (uint32_t)(tid * 16 + j * 4096), asrc + tid * 4 + j * 1024); \
    _Pragma("unroll") for (int j = 0; j < 4; j++)                              \
      CP_ASYNC16(bB + (uint32_t)(tid * 16 + j * 4096), bsrc + tid * 4 + j * 1024); \
    CP_COMMIT();                                                               \
  }

  float4 acc[4][4];
#pragma unroll
  for (int i = 0; i < 4; i++)
#pragma unroll
    for (int j = 0; j < 4; j++) acc[i][j] = make_float4(0.f, 0.f, 0.f, 0.f);

  G_ISSUE(0, 0);
  G_ISSUE(TKK, 1);

  const int niter = K / TKK;
  for (int it = 0; it < niter; it++) {
    if (it == niter - 1) CP_WAIT(0); else CP_WAIT(1);
    __syncthreads();
    if (it + 2 < niter) G_ISSUE((it + 2) * TKK, (it + 2) % 3);

    const float* As_ = Asm + (it % 3) * TILEF;
    const float* Bs_ = Bsm + (it % 3) * TILEF;
#pragma unroll
    for (int ki = 0; ki < 4; ki++) {
      uint4 a[4];
      uint2 b[4];
#pragma unroll
      for (int i = 0; i < 4; i++)
        a[i] = *(const uint4*)&As_[(((wm * 4 + i) * 4 + ki) * 32 + lane) * 4];
#pragma unroll
      for (int j = 0; j < 4; j++)
        b[j] = *(const uint2*)&Bs_[((ki * 16 + wn * 4 + j) * 32 + lane) * 2];
#pragma unroll
      for (int i = 0; i < 4; i++)
#pragma unroll
        for (int j = 0; j < 4; j++) mma_tf32(acc[i][j], a[i], b[j]);
    }
  }

  __syncthreads();
  {
    const int g = lane >> 2, t = lane & 3;
#pragma unroll
    for (int i = 0; i < 4; i++)
#pragma unroll
      for (int j = 0; j < 4; j++) {
        int r0 = wm * 64 + i * 16 + g;
        int cc = wn * 32 + j * 8 + t * 2;
        *(float2*)&smg[r0 * LDS + cc] = make_float2(acc[i][j].x, acc[i][j].y);
        *(float2*)&smg[(r0 + 8) * LDS + cc] = make_float2(acc[i][j].z, acc[i][j].w);
      }
  }
  __syncthreads();

#pragma unroll
  for (int i = 0; i < 16; i++) {
    int f = tid + i * 256;
    int r = f >> 5, c4 = (f & 31) * 4;
    float4 v = *(const float4*)&smg[r * LDS + c4];
    if (mode == 1) {
      int gc = bn + c4;
      float s = ((gc % 320) < 128) ? 0.125f : 1.0f;
      v.x = tf32r(v.x * s); v.y = tf32r(v.y * s);
      v.z = tf32r(v.z * s); v.w = tf32r(v.w * s);
    }
    *(float4*)&C[(size_t)(bm + r) * N + bn + c4] = v;
  }
}

// ---------------------------------------------------------------------------
// Fully in-register differential attention.
// 256 thr / 8 warps, 128-q tile, 64-key tiles (packed), 2-stage cp.async.
// Softmax on acc fragments; P via quad-shuffle conversion; Q/O in registers.
// ---------------------------------------------------------------------------
#define KVTF 12288
#define ATTN_SMEM (2 * KVTF * (int)sizeof(float))  // 98,304 B

__device__ __forceinline__ void attn_path(
    const uint4* __restrict__ qf, const float* __restrict__ Kp,
    const float* __restrict__ Vp, float4* __restrict__ O,
    float& slo, float& shi, int lane, int rowlo, int j0, bool needmask) {
  float4 s[8];
#pragma unroll
  for (int nb = 0; nb < 8; nb++) s[nb] = make_float4(0.f, 0.f, 0.f, 0.f);
#pragma unroll
  for (int kk = 0; kk < 8; kk++) {
    uint4 a = qf[kk];
#pragma unroll
    for (int nb = 0; nb < 8; nb++) {
      uint2 bb = *(const uint2*)&Kp[(nb * 8 + kk) * 64 + lane * 2];
      mma_tf32(s[nb], a, bb);
    }
  }
  const int t = lane & 3;
  uint4 P[8];
#pragma unroll
  for (int nb = 0; nb < 8; nb++) {
    float p0 = __expf(s[nb].x), p1 = __expf(s[nb].y);
    float p2 = __expf(s[nb].z), p3 = __expf(s[nb].w);
    if (needmask) {
      int jc = j0 + nb * 8 + 2 * t;
      int ihi = rowlo + 8;
      if (jc > rowlo)     p0 = 0.f;
      if (jc + 1 > rowlo) p1 = 0.f;
      if (jc > ihi)       p2 = 0.f;
      if (jc + 1 > ihi)   p3 = 0.f;
    }
    slo += p0 + p1;
    shi += p2 + p3;
    float4 r = make_float4(tf32r(p0), tf32r(p1), tf32r(p2), tf32r(p3));
    float4 a4 = cvt_c2a(r, lane);
    P[nb] = *(uint4*)&a4;
  }
#pragma unroll
  for (int kk = 0; kk < 8; kk++) {
    uint4 a = P[kk];
#pragma unroll
    for (int db = 0; db < 8; db++) {
      uint2 bb = *(const uint2*)&Vp[(kk * 8 + db) * 64 + lane * 2];
      mma_tf32(O[db], a, bb);
    }
  }
}

__global__ __launch_bounds__(256) void attn_kernel(
    const float* __restrict__ lam_p, float* __restrict__ attn_out) {
  extern __shared__ float sm[];
  const uint32_t s0 = smem_u32(sm);
  const int tid  = threadIdx.x;
  const int lane = tid & 31;
  const int warp = tid >> 5;
  const int g    = lane >> 2;
  const int t    = lane & 3;
  const int wr   = warp * 16;
  const int b    = blockIdx.z;
  const int h    = blockIdx.y;
  const int i0   = (int)(gridDim.x - 1 - blockIdx.x) * 128;  // heavy first
  const float lamc = fminf(fmaxf(lam_p[h], 0.0f), 1.0f);

  const float* qbase  = g_qkv + (size_t)b * NT * QKVN + (size_t)h * 320;
  const float* kvbase = g_kvp + (size_t)((b * NH + h) * 32) * KVTF;

#define ATT_ISSUE_KV(jb, s)                                                    \
  {                                                                            \
    const float* src = kvbase + (size_t)(jb) * KVTF;                           \
    uint32_t dst = s0 + (uint32_t)(s) * (KVTF * 4);                            \
    _Pragma("unroll") for (int i = 0; i < 12; i++)                             \
      CP_ASYNC16(dst + (uint32_t)(tid * 16 + i * 4096), src + tid * 4 + i * 1024); \
    CP_COMMIT();                                                               \
  }

  // ---- Q prologue: stage row-major in the two KV buffers, lift to regs ----
  {
#pragma unroll
    for (int i = 0; i < 8; i++) {
      int f = tid + i * 256;
      int r = f >> 4, c4 = (f & 15) * 4;
      CP_ASYNC16(s0 + (uint32_t)(r * 64 + c4) * 4,
                 &qbase[(size_t)(i0 + r) * QKVN + c4]);
      CP_ASYNC16(s0 + (uint32_t)(KVTF + r * 64 + c4) * 4,
                 &qbase[(size_t)(i0 + r) * QKVN + 64 + c4]);
    }
    CP_COMMIT();
    CP_WAIT(0);
  }
  __syncthreads();
  uint4 q1f[8], q2f[8];
#pragma unroll
  for (int kk = 0; kk < 8; kk++) {
    int r0 = (wr + g) * 64 + kk * 8 + t;
    float4 v;
    v.x = sm[r0];
    v.y = sm[r0 + 8 * 64];
    v.z = sm[r0 + 4];
    v.w = sm[r0 + 8 * 64 + 4];
    q1f[kk] = *(uint4*)&v;
    v.x = sm[KVTF + r0];
    v.y = sm[KVTF + r0 + 8 * 64];
    v.z = sm[KVTF + r0 + 4];
    v.w = sm[KVTF + r0 + 8 * 64 + 4];
    q2f[kk] = *(uint4*)&v;
  }
  __syncthreads();

  ATT_ISSUE_KV(0, 0);
  ATT_ISSUE_KV(1, 1);

  float4 O1[8], O2[8];
#pragma unroll
  for (int i = 0; i < 8; i++) {
    O1[i] = make_float4(0.f, 0.f, 0.f, 0.f);
    O2[i] = make_float4(0.f, 0.f, 0.f, 0.f);
  }
  float sl1lo = 0.f, sl1hi = 0.f, sl2lo = 0.f, sl2hi = 0.f;
  const int rowlo = i0 + wr + g;

  const int ntiles = i0 / 64 + 2;
  for (int tt = 0; tt < ntiles; tt++) {
    if (tt == ntiles - 1) CP_WAIT(0); else CP_WAIT(1);
    __syncthreads();
    const int j0 = tt * 64;
    if (j0 <= i0 + wr + 15) {  // warp-uniform: strip has valid cols
      const float* kv = sm + (tt & 1) * KVTF;
      const bool needmask = (j0 + 63 > i0 + wr);
      attn_path(q1f, kv,        kv + 8192, O1, sl1lo, sl1hi, lane, rowlo, j0, needmask);
      attn_path(q2f, kv + 4096, kv + 8192, O2, sl2lo, sl2hi, lane, rowlo, j0, needmask);
    }
    __syncthreads();
    if (tt + 2 < ntiles) ATT_ISSUE_KV(tt + 2, tt & 1);
  }

  // ---- quad-reduce row sums (rows g, g+8 of this warp strip) ----
  sl1lo += __shfl_xor_sync(0xffffffffu, sl1lo, 1);
  sl1lo += __shfl_xor_sync(0xffffffffu, sl1lo, 2);
  sl1hi += __shfl_xor_sync(0xffffffffu, sl1hi, 1);
  sl1hi += __shfl_xor_sync(0xffffffffu, sl1hi, 2);
  sl2lo += __shfl_xor_sync(0xffffffffu, sl2lo, 1);
  sl2lo += __shfl_xor_sync(0xffffffffu, sl2lo, 2);
  sl2hi += __shfl_xor_sync(0xffffffffu, sl2hi, 1);
  sl2hi += __shfl_xor_sync(0xffffffffu, sl2hi, 2);
  const float i1lo = 1.0f / sl1lo, i1hi = 1.0f / sl1hi;
  const float i2lo = lamc / sl2lo, i2hi = lamc / sl2hi;

  // ---- combine + convert + packed-A write to g_attn ----
  const int grow = b * NT + i0 + wr;
  const int mb = grow >> 7;
  const int mi = (grow >> 4) & 7;
#pragma unroll
  for (int db = 0; db < 8; db++) {
    float4 c;
    c.x = O1[db].x * i1lo - O2[db].x * i2lo;
    c.y = O1[db].y * i1lo - O2[db].y * i2lo;
    c.z = O1[db].z * i1hi - O2[db].z * i2hi;
    c.w = O1[db].w * i1hi - O2[db].w * i2hi;
    float4 a4 = cvt_c2a(c, lane);
    a4.x = tf32r(a4.x); a4.y = tf32r(a4.y);
    a4.z = tf32r(a4.z); a4.w = tf32r(a4.w);
    int gcol = h * 64 + db * 8;
    int kb = gcol >> 5, ki = (gcol >> 3) & 3;
    size_t fi = (((size_t)(mb * 32 + kb) * 32) + mi * 4 + ki) * 32 + lane;
    *(float4*)&attn_out[fi * 4] = a4;
  }
}

// ---------------------------------------------------------------------------
extern "C" void kernel_launch(void* const* d_in, const int* in_sizes, int n_in,
                              void* d_out, int out_size) {
  const float* x    = (const float*)d_in[0];
  // d_in[1] = mask: exact causal additive mask; handled analytically.
  const float* Wqkv = (const float*)d_in[2];
  const float* Wout = (const float*)d_in[3];
  const float* lam  = (const float*)d_in[4];
  float* out = (float*)d_out;

  float *qkv_d, *attn_d, *x_d, *wq_d, *wo_d, *kvp_d;
  cudaGetSymbolAddress((void**)&qkv_d, g_qkv);
  cudaGetSymbolAddress((void**)&attn_d, g_attn);
  cudaGetSymbolAddress((void**)&x_d, g_x);
  cudaGetSymbolAddress((void**)&wq_d, g_wq);
  cudaGetSymbolAddress((void**)&wo_d, g_wo);
  cudaGetSymbolAddress((void**)&kvp_d, g_kvp);

  cudaFuncSetAttribute(gemm_tc, cudaFuncAttributeMaxDynamicSharedMemorySize, GEMM_SMEM);
  cudaFuncSetAttribute(attn_kernel, cudaFuncAttributeMaxDynamicSharedMemorySize, ATTN_SMEM);

  // 0) permute + tf32-round inputs into fragment-packed layouts
  permute_A_kernel<<<(BTOT / 128) * (NDM / 32) * 1024 / 256, 256>>>(x, x_d, BTOT, NDM);
  permute_B_kernel<<<(NDM / 32) * (QKVN / 128) * 2048 / 256, 256>>>(Wqkv, wq_d, NDM, QKVN);
  permute_B_kernel<<<(NDM / 32) * (NDM / 128) * 2048 / 256, 256>>>(Wout, wo_d, NDM, NDM);

  // 1) qkv = x @ W_qkv  (epilogue: scale q cols + tf32 round; row-major out)
  {
    dim3 grid(QKVN / TNN, BTOT / TMM);  // (40, 32)
    gemm_tc<<<grid, 256, GEMM_SMEM>>>(x_d, wq_d, qkv_d, BTOT, QKVN, NDM, 1);
  }

  // 1b) pack K1/K2/V into mma B-fragment tiles
  {
    dim3 grid(24, NBATCH * NH * 32);  // 6144 frag-lanes / 256, 1024 tiles
    permute_KV_kernel<<<grid, 256>>>(qkv_d, kvp_d);
  }

  // 2) differential attention (in-register softmax; packed output)
  {
    dim3 grid(NT / 128, NH, NBATCH);  // (16, 16, 2)
    attn_kernel<<<grid, 256, ATTN_SMEM>>>(lam, attn_d);
  }

  // 3) out = attn @ W_out
  {
    dim3 grid(NDM / TNN, BTOT / TMM);  // (8, 32)
    gemm_tc<<<grid, 256, GEMM_SMEM>>>(attn_d, wo_d, out, BTOT, NDM, NDM, 0);
  }
}

// round 10
// speedup vs baseline: 2.5998x; 1.1059x over previous
#include <cuda_runtime.h>
#include <mma.h>
#include <math.h>
#include <cstdint>

using namespace nvcuda;

#define NBATCH 2
#define NT     2048
#define NDM    1024
#define NH     16
#define ND     64
#define QKVN   (NH * 5 * ND)   // 5120
#define BTOT   (NBATCH * NT)   // 4096

// Scratch (device-global; allocation-free per harness rules)
__device__ float g_qA [(size_t)NBATCH * NH * 16 * 16384];  // Q1|Q2 A-frag packed
__device__ float g_attn[(size_t)BTOT * NDM];               // PACKED A-frag layout
__device__ float g_x  [(size_t)BTOT * NDM];                // PACKED A-frag layout
__device__ float g_wq [(size_t)NDM * QKVN];                // PACKED B-frag layout
__device__ float g_wo [(size_t)NDM * NDM];                 // PACKED B-frag layout
__device__ float g_kvp[(size_t)NBATCH * NH * 32 * 12288];  // packed K1|K2|V tiles

__device__ __forceinline__ float tf32r(float x) { return wmma::__float_to_tf32(x); }

__device__ __forceinline__ uint32_t smem_u32(const void* p) {
  uint32_t a;
  asm("{ .reg .u64 t; cvta.to.shared.u64 t, %1; cvt.u32.u64 %0, t; }"
      : "=r"(a) : "l"(p));
  return a;
}

#define CP_ASYNC16(dst, src) \
  asm volatile("cp.async.cg.shared.global [%0], [%1], 16;" :: "r"(dst), "l"(src))
#define CP_COMMIT() asm volatile("cp.async.commit_group;" ::: "memory")
#define CP_WAIT(n)  asm volatile("cp.async.wait_group %0;" :: "n"(n) : "memory")

__device__ __forceinline__ void mma_tf32(float4& d, const uint4& a, const uint2& b) {
  asm volatile(
      "mma.sync.aligned.m16n8k8.row.col.f32.tf32.tf32.f32 "
      "{%0,%1,%2,%3}, {%4,%5,%6,%7}, {%8,%9}, {%0,%1,%2,%3};\n"
      : "+f"(d.x), "+f"(d.y), "+f"(d.z), "+f"(d.w)
      : "r"(a.x), "r"(a.y), "r"(a.z), "r"(a.w), "r"(b.x), "r"(b.y));
}

// acc layout (c0=(g,2t) c1=(g,2t+1) c2=(g+8,2t) c3=(g+8,2t+1)) ->
// A-operand layout (a0=(g,t) a1=(g+8,t) a2=(g,t+4) a3=(g+8,t+4)); quad shuffle.
__device__ __forceinline__ float4 cvt_c2a(float4 c, int lane) {
  int tA = (lane & ~3) | ((lane & 3) >> 1);
  int tB = tA + 2;
  float e0 = __shfl_sync(0xffffffffu, c.x, tA);
  float e1 = __shfl_sync(0xffffffffu, c.y, tA);
  float e2 = __shfl_sync(0xffffffffu, c.z, tA);
  float e3 = __shfl_sync(0xffffffffu, c.w, tA);
  float f0 = __shfl_sync(0xffffffffu, c.x, tB);
  float f1 = __shfl_sync(0xffffffffu, c.y, tB);
  float f2 = __shfl_sync(0xffffffffu, c.z, tB);
  float f3 = __shfl_sync(0xffffffffu, c.w, tB);
  bool odd = lane & 1;
  float4 a;
  a.x = odd ? e1 : e0;
  a.y = odd ? e3 : e2;
  a.z = odd ? f1 : f0;
  a.w = odd ? f3 : f2;
  return a;
}

// ---------------------------------------------------------------------------
// Input permutes (validated R8): A-frag and B-frag packing.
// ---------------------------------------------------------------------------
__global__ void permute_A_kernel(const float* __restrict__ src,
                                 float* __restrict__ dst, int M, int K) {
  int idx = blockIdx.x * blockDim.x + threadIdx.x;
  int l  = idx & 31;
  int fi = (idx >> 5) & 31;
  int blk = idx >> 10;
  int Kb = K >> 5;
  int kb = blk % Kb, mb = blk / Kb;
  if (mb >= (M >> 7)) return;
  int mi = fi >> 2, ki = fi & 3;
  int g = l >> 2, t = l & 3;
  size_t r = mb * 128 + mi * 16 + g;
  size_t c = kb * 32 + ki * 8 + t;
  float4 v;
  v.x = tf32r(src[r * K + c]);
  v.y = tf32r(src[(r + 8) * K + c]);
  v.z = tf32r(src[r * K + c + 4]);
  v.w = tf32r(src[(r + 8) * K + c + 4]);
  ((float4*)dst)[idx] = v;
}

__global__ void permute_B_kernel(const float* __restrict__ src,
                                 float* __restrict__ dst, int K, int N) {
  int idx = blockIdx.x * blockDim.x + threadIdx.x;
  int l  = idx & 31;
  int fi = (idx >> 5) & 63;
  int blk = idx >> 11;
  int Nb = N >> 7;
  int nb = blk % Nb, kb = blk / Nb;
  if (kb >= (K >> 5)) return;
  int ki = fi >> 4, ni = fi & 15;
  int g = l >> 2, t = l & 3;
  size_t k = kb * 32 + ki * 8 + t;
  size_t n = nb * 128 + ni * 8 + g;
  float2 v;
  v.x = tf32r(src[k * N + n]);
  v.y = tf32r(src[(k + 4) * N + n]);
  ((float2*)dst)[idx] = v;
}

// ---------------------------------------------------------------------------
// Hand-mma TF32 GEMM (R8-proven core). 128x128x32, 3-stage, 2 CTA/SM.
// mode 0: row-major fp32 store to C.
// mode 1: QKV epilogue — Q1/Q2 -> A-frag packed (scaled) into C,
//                        K1/K2/V -> B-frag packed tiles into C2.
// ---------------------------------------------------------------------------
#define TMM 128
#define TNN 128
#define TKK 32
#define TILEF 4096
#define GEMM_SMEM (3 * 2 * TILEF * (int)sizeof(float))
#define LDS 132

__global__ __launch_bounds__(256, 2) void gemm_tc(
    const float* __restrict__ Apk, const float* __restrict__ Bpk,
    float* __restrict__ C, float* __restrict__ C2,
    int M, int N, int K, int mode) {
  extern __shared__ float smg[];
  float* Asm = smg;
  float* Bsm = smg + 3 * TILEF;
  const uint32_t sA = smem_u32(Asm);
  const uint32_t sB = smem_u32(Bsm);

  const int tid  = threadIdx.x;
  const int lane = tid & 31;
  const int warp = tid >> 5;
  const int wm   = warp & 1;
  const int wn   = warp >> 1;
  const int bm   = blockIdx.y * TMM;
  const int bn   = blockIdx.x * TNN;
  const int Kb   = K >> 5;
  const int Nb   = N >> 7;

#define G_ISSUE(k0, s)                                                         \
  {                                                                            \
    const float* asrc = Apk + ((size_t)(bm >> 7) * Kb + ((k0) >> 5)) * TILEF;  \
    const float* bsrc = Bpk + ((size_t)((k0) >> 5) * Nb + (bn >> 7)) * TILEF;  \
    uint32_t aB = sA + (uint32_t)(s) * (TILEF * 4);                            \
    uint32_t bB = sB + (uint32_t)(s) * (TILEF * 4);                            \
    _Pragma("unroll") for (int j = 0; j < 4; j++)                              \
      CP_ASYNC16(aB + (uint32_t)(tid * 16 + j * 4096), asrc + tid * 4 + j * 1024); \
    _Pragma("unroll") for (int j = 0; j < 4; j++)                              \
      CP_ASYNC16(bB + (uint32_t)(tid * 16 + j * 4096), bsrc + tid * 4 + j * 1024); \
    CP_COMMIT();                                                               \
  }

  float4 acc[4][4];
#pragma unroll
  for (int i = 0; i < 4; i++)
#pragma unroll
    for (int j = 0; j < 4; j++) acc[i][j] = make_float4(0.f, 0.f, 0.f, 0.f);

  G_ISSUE(0, 0);
  G_ISSUE(TKK, 1);

  const int niter = K / TKK;
  for (int it = 0; it < niter; it++) {
    if (it == niter - 1) CP_WAIT(0); else CP_WAIT(1);
    __syncthreads();
    if (it + 2 < niter) G_ISSUE((it + 2) * TKK, (it + 2) % 3);

    const float* As_ = Asm + (it % 3) * TILEF;
    const float* Bs_ = Bsm + (it % 3) * TILEF;
#pragma unroll
    for (int ki = 0; ki < 4; ki++) {
      uint4 a[4];
      uint2 b[4];
#pragma unroll
      for (int i = 0; i < 4; i++)
        a[i] = *(const uint4*)&As_[(((wm * 4 + i) * 4 + ki) * 32 + lane) * 4];
#pragma unroll
      for (int j = 0; j < 4; j++)
        b[j] = *(const uint2*)&Bs_[((ki * 16 + wn * 4 + j) * 32 + lane) * 2];
#pragma unroll
      for (int i = 0; i < 4; i++)
#pragma unroll
        for (int j = 0; j < 4; j++) mma_tf32(acc[i][j], a[i], b[j]);
    }
  }

  // stage C tile in smem
  __syncthreads();
  {
    const int g = lane >> 2, t = lane & 3;
#pragma unroll
    for (int i = 0; i < 4; i++)
#pragma unroll
      for (int j = 0; j < 4; j++) {
        int r0 = wm * 64 + i * 16 + g;
        int cc = wn * 32 + j * 8 + t * 2;
        *(float2*)&smg[r0 * LDS + cc] = make_float2(acc[i][j].x, acc[i][j].y);
        *(float2*)&smg[(r0 + 8) * LDS + cc] = make_float2(acc[i][j].z, acc[i][j].w);
      }
  }
  __syncthreads();

  if (mode == 0) {
#pragma unroll
    for (int i = 0; i < 16; i++) {
      int f = tid + i * 256;
      int r = f >> 5, c4 = (f & 31) * 4;
      float4 v = *(const float4*)&smg[r * LDS + c4];
      *(float4*)&C[(size_t)(bm + r) * N + bn + c4] = v;
    }
  } else {
    // fused QKV packing epilogue
    const int b    = bm >> 11;
    const int tok0 = bm & 2047;
    const int itq  = tok0 >> 7;
    const int jb0  = tok0 >> 6;
#pragma unroll
    for (int hc = 0; hc < 2; hc++) {
      const int gcol0 = bn + hc * 64;
      const int h  = gcol0 / 320;
      const int c5 = gcol0 % 320;
      const float* sbase = smg + hc * 64;
      if (c5 < 128) {
        // Q1/Q2 -> A-frag packed, scaled by 1/8
        const int path = c5 >> 6;
        float* qdst = C + (((size_t)(b * NH + h) * 16 + itq) * 16384) + path * 8192;
#pragma unroll
        for (int s = 0; s < 8; s++) {
          int f4 = tid + s * 256;
          int l2 = f4 & 31, kk = (f4 >> 5) & 7, wrp = f4 >> 8;
          int gg = l2 >> 2, tp = l2 & 3;
          int rA = wrp * 16 + gg;
          float4 v;
          v.x = tf32r(sbase[rA * LDS + kk * 8 + tp] * 0.125f);
          v.y = tf32r(sbase[(rA + 8) * LDS + kk * 8 + tp] * 0.125f);
          v.z = tf32r(sbase[rA * LDS + kk * 8 + 4 + tp] * 0.125f);
          v.w = tf32r(sbase[(rA + 8) * LDS + kk * 8 + 4 + tp] * 0.125f);
          *(float4*)&qdst[(size_t)f4 * 4] = v;
        }
      } else if (c5 < 256) {
        // K1/K2 -> B-frag packed
        const int mat = (c5 - 128) >> 6;
        float2* kv2 = (float2*)C2;
#pragma unroll
        for (int jl = 0; jl < 2; jl++) {
          size_t t2 = ((size_t)(b * NH + h) * 32 + jb0 + jl) * 6144;
#pragma unroll
          for (int s = 0; s < 8; s++) {
            int f2 = tid + s * 256;
            int l2 = f2 & 31, kkf = (f2 >> 5) & 7, nb = f2 >> 8;
            int gg = l2 >> 2, tp = l2 & 3;
            int rl = jl * 64 + nb * 8 + gg;
            float2 v;
            v.x = tf32r(sbase[rl * LDS + kkf * 8 + tp]);
            v.y = tf32r(sbase[rl * LDS + kkf * 8 + 4 + tp]);
            kv2[t2 + (mat * 64 + nb * 8 + kkf) * 32 + l2] = v;
          }
        }
      } else {
        // V -> B-frag packed (transposed role)
        float2* kv2 = (float2*)C2;
#pragma unroll
        for (int jl = 0; jl < 2; jl++) {
          size_t t2 = ((size_t)(b * NH + h) * 32 + jb0 + jl) * 6144;
#pragma unroll
          for (int s = 0; s < 8; s++) {
            int f2 = tid + s * 256;
            int l2 = f2 & 31, db = (f2 >> 5) & 7, kk = f2 >> 8;
            int gg = l2 >> 2, tp = l2 & 3;
            int rl = jl * 64 + kk * 8 + tp;
            int cl = db * 8 + gg;
            float2 v;
            v.x = tf32r(sbase[rl * LDS + cl]);
            v.y = tf32r(sbase[(rl + 4) * LDS + cl]);
            kv2[t2 + (128 + kk * 8 + db) * 32 + l2] = v;
          }
        }
      }
    }
  }
}

// ---------------------------------------------------------------------------
// Path-parallel in-register differential attention. 512 threads:
// warps 0-7 = softmax path 1, warps 8-15 = path 2 (8 warps x 16 q-rows each).
// Q frags loaded directly from g_qA; KV tiles cp.async 2-stage.
// ---------------------------------------------------------------------------
#define KVTF 12288
#define ATTN_SMEM (2 * KVTF * (int)sizeof(float))  // 98,304 B

__device__ __forceinline__ void attn_path(
    const uint4* __restrict__ qf, const float* __restrict__ Kp,
    const float* __restrict__ Vp, float4* __restrict__ O,
    float& slo, float& shi, int lane, int rowlo, int j0, bool needmask) {
  float4 s[8];
#pragma unroll
  for (int nb = 0; nb < 8; nb++) s[nb] = make_float4(0.f, 0.f, 0.f, 0.f);
#pragma unroll
  for (int kk = 0; kk < 8; kk++) {
    uint4 a = qf[kk];
#pragma unroll
    for (int nb = 0; nb < 8; nb++) {
      uint2 bb = *(const uint2*)&Kp[(nb * 8 + kk) * 64 + lane * 2];
      mma_tf32(s[nb], a, bb);
    }
  }
  const int t = lane & 3;
  uint4 P[8];
#pragma unroll
  for (int nb = 0; nb < 8; nb++) {
    float p0 = __expf(s[nb].x), p1 = __expf(s[nb].y);
    float p2 = __expf(s[nb].z), p3 = __expf(s[nb].w);
    if (needmask) {
      int jc = j0 + nb * 8 + 2 * t;
      int ihi = rowlo + 8;
      if (jc > rowlo)     p0 = 0.f;
      if (jc + 1 > rowlo) p1 = 0.f;
      if (jc > ihi)       p2 = 0.f;
      if (jc + 1 > ihi)   p3 = 0.f;
    }
    slo += p0 + p1;
    shi += p2 + p3;
    float4 r = make_float4(tf32r(p0), tf32r(p1), tf32r(p2), tf32r(p3));
    float4 a4 = cvt_c2a(r, lane);
    P[nb] = *(uint4*)&a4;
  }
#pragma unroll
  for (int kk = 0; kk < 8; kk++) {
    uint4 a = P[kk];
#pragma unroll
    for (int db = 0; db < 8; db++) {
      uint2 bb = *(const uint2*)&Vp[(kk * 8 + db) * 64 + lane * 2];
      mma_tf32(O[db], a, bb);
    }
  }
}

__global__ __launch_bounds__(512) void attn_kernel(
    const float* __restrict__ lam_p, float* __restrict__ attn_out) {
  extern __shared__ float sm[];
  const uint32_t s0 = smem_u32(sm);
  const int tid  = threadIdx.x;
  const int lane = tid & 31;
  const int warp = tid >> 5;
  const int path = warp >> 3;
  const int wl   = warp & 7;
  const int g    = lane >> 2;
  const int b    = blockIdx.z;
  const int h    = blockIdx.y;
  const int i0   = (int)(gridDim.x - 1 - blockIdx.x) * 128;  // heavy first
  const float lamc = fminf(fmaxf(lam_p[h], 0.0f), 1.0f);

  const float* kvbase = g_kvp + (size_t)((b * NH + h) * 32) * KVTF;

#define ATT_ISSUE_KV(jb, s)                                                    \
  {                                                                            \
    const float* src = kvbase + (size_t)(jb) * KVTF;                           \
    uint32_t dst = s0 + (uint32_t)(s) * (KVTF * 4);                            \
    _Pragma("unroll") for (int i = 0; i < 6; i++)                              \
      CP_ASYNC16(dst + (uint32_t)(tid * 16 + i * 8192), src + tid * 4 + i * 2048); \
    CP_COMMIT();                                                               \
  }

  ATT_ISSUE_KV(0, 0);
  ATT_ISSUE_KV(1, 1);

  // Q fragments: direct coalesced loads from packed g_qA
  uint4 qf[8];
  {
    const float* gq = g_qA +
        (((size_t)(b * NH + h) * 16 + (i0 >> 7)) * 16384) + path * 8192 + wl * 1024;
#pragma unroll
    for (int kk = 0; kk < 8; kk++)
      qf[kk] = *(const uint4*)&gq[kk * 128 + lane * 4];
  }

  float4 O[8];
#pragma unroll
  for (int i = 0; i < 8; i++) O[i] = make_float4(0.f, 0.f, 0.f, 0.f);
  float slo = 0.f, shi = 0.f;
  const int rowlo = i0 + wl * 16 + g;

  const int ntiles = i0 / 64 + 2;
  for (int tt = 0; tt < ntiles; tt++) {
    if (tt == ntiles - 1) CP_WAIT(0); else CP_WAIT(1);
    __syncthreads();
    const int j0 = tt * 64;
    if (j0 <= i0 + wl * 16 + 15) {  // warp-uniform: strip has valid cols
      const float* kv = sm + (tt & 1) * KVTF;
      const bool needmask = (j0 + 63 > i0 + wl * 16);
      attn_path(qf, kv + path * 4096, kv + 8192, O, slo, shi, lane, rowlo, j0, needmask);
    }
    __syncthreads();
    if (tt + 2 < ntiles) ATT_ISSUE_KV(tt + 2, tt & 1);
  }

  // quad-reduce row sums (rows g, g+8 of this warp's strip)
  slo += __shfl_xor_sync(0xffffffffu, slo, 1);
  slo += __shfl_xor_sync(0xffffffffu, slo, 2);
  shi += __shfl_xor_sync(0xffffffffu, shi, 1);
  shi += __shfl_xor_sync(0xffffffffu, shi, 2);
  const float ilo = (path ? lamc : 1.0f) / slo;
  const float ihi = (path ? lamc : 1.0f) / shi;

  // path 2 publishes normalized O; path 1 combines + packs + stores
  if (path == 1) {
#pragma unroll
    for (int db = 0; db < 8; db++) {
      float4 o;
      o.x = O[db].x * ilo; o.y = O[db].y * ilo;
      o.z = O[db].z * ihi; o.w = O[db].w * ihi;
      *(float4*)&sm[((wl * 8 + db) * 32 + lane) * 4] = o;
    }
  }
  __syncthreads();
  if (path == 0) {
    const int grow = b * NT + i0 + wl * 16;
    const int mb = grow >> 7;
    const int mi = (grow >> 4) & 7;
#pragma unroll
    for (int db = 0; db < 8; db++) {
      float4 o2 = *(const float4*)&sm[((wl * 8 + db) * 32 + lane) * 4];
      float4 c;
      c.x = O[db].x * ilo - o2.x;
      c.y = O[db].y * ilo - o2.y;
      c.z = O[db].z * ihi - o2.z;
      c.w = O[db].w * ihi - o2.w;
      float4 a4 = cvt_c2a(c, lane);
      a4.x = tf32r(a4.x); a4.y = tf32r(a4.y);
      a4.z = tf32r(a4.z); a4.w = tf32r(a4.w);
      int gcol = h * 64 + db * 8;
      int kb = gcol >> 5, ki = (gcol >> 3) & 3;
      size_t fi = (((size_t)(mb * 32 + kb) * 32) + mi * 4 + ki) * 32 + lane;
      *(float4*)&attn_out[fi * 4] = a4;
    }
  }
}

// ---------------------------------------------------------------------------
extern "C" void kernel_launch(void* const* d_in, const int* in_sizes, int n_in,
                              void* d_out, int out_size) {
  const float* x    = (const float*)d_in[0];
  // d_in[1] = mask: exact causal additive mask; handled analytically.
  const float* Wqkv = (const float*)d_in[2];
  const float* Wout = (const float*)d_in[3];
  const float* lam  = (const float*)d_in[4];
  float* out = (float*)d_out;

  float *qA_d, *attn_d, *x_d, *wq_d, *wo_d, *kvp_d;
  cudaGetSymbolAddress((void**)&qA_d, g_qA);
  cudaGetSymbolAddress((void**)&attn_d, g_attn);
  cudaGetSymbolAddress((void**)&x_d, g_x);
  cudaGetSymbolAddress((void**)&wq_d, g_wq);
  cudaGetSymbolAddress((void**)&wo_d, g_wo);
  cudaGetSymbolAddress((void**)&kvp_d, g_kvp);

  cudaFuncSetAttribute(gemm_tc, cudaFuncAttributeMaxDynamicSharedMemorySize, GEMM_SMEM);
  cudaFuncSetAttribute(attn_kernel, cudaFuncAttributeMaxDynamicSharedMemorySize, ATTN_SMEM);

  // 0) permute + tf32-round inputs into fragment-packed layouts
  permute_A_kernel<<<(BTOT / 128) * (NDM / 32) * 1024 / 256, 256>>>(x, x_d, BTOT, NDM);
  permute_B_kernel<<<(NDM / 32) * (QKVN / 128) * 2048 / 256, 256>>>(Wqkv, wq_d, NDM, QKVN);
  permute_B_kernel<<<(NDM / 32) * (NDM / 128) * 2048 / 256, 256>>>(Wout, wo_d, NDM, NDM);

  // 1) qkv = x @ W_qkv  (fused epilogue: Q -> A-frags scaled, K/V -> packed tiles)
  {
    dim3 grid(QKVN / TNN, BTOT / TMM);  // (40, 32)
    gemm_tc<<<grid, 256, GEMM_SMEM>>>(x_d, wq_d, qA_d, kvp_d, BTOT, QKVN, NDM, 1);
  }

  // 2) differential attention (path-parallel, in-register softmax)
  {
    dim3 grid(NT / 128, NH, NBATCH);  // (16, 16, 2)
    attn_kernel<<<grid, 512, ATTN_SMEM>>>(lam, attn_d);
  }

  // 3) out = attn @ W_out
  {
    dim3 grid(NDM / TNN, BTOT / TMM);  // (8, 32)
    gemm_tc<<<grid, 256, GEMM_SMEM>>>(attn_d, wo_d, out, nullptr, BTOT, NDM, NDM, 0);
  }
}

// round 14
// speedup vs baseline: 4.5920x; 1.7663x over previous
#include <cuda_runtime.h>
#include <cuda_fp16.h>
#include <math.h>
#include <cstdint>

#define NBATCH 2
#define NT     2048
#define NDM    1024
#define NH     16
#define ND     64
#define QKVN   (NH * 5 * ND)   // 5120
#define BTOT   (NBATCH * NT)   // 4096

// Scratch (device-global; allocation-free per harness rules)
__device__ __half g_qA [(size_t)NBATCH * NH * 16 * 2 * 8192]; // Q1|Q2 A-frag fp16
__device__ __half g_attn[(size_t)BTOT * NDM];                 // A-frag fp16
__device__ __half g_x  [(size_t)BTOT * NDM];                  // A-frag fp16
__device__ __half g_wq [(size_t)NDM * QKVN];                  // B-frag fp16
__device__ __half g_wo [(size_t)NDM * NDM];                   // B-frag fp16
__device__ __half g_kvp[(size_t)NBATCH * NH * 32 * 12288];    // K1|K2|V B-frag tiles

__device__ __forceinline__ uint32_t f22h(float a, float b) {
  __half2 h = __floats2half2_rn(a, b);
  return *(uint32_t*)&h;
}

__device__ __forceinline__ uint32_t smem_u32(const void* p) {
  uint32_t a;
  asm("{ .reg .u64 t; cvta.to.shared.u64 t, %1; cvt.u32.u64 %0, t; }"
      : "=r"(a) : "l"(p));
  return a;
}

#define CP_ASYNC16(dst, src) \
  asm volatile("cp.async.cg.shared.global [%0], [%1], 16;" :: "r"(dst), "l"(src))
#define CP_COMMIT() asm volatile("cp.async.commit_group;" ::: "memory")
#define CP_WAIT(n)  asm volatile("cp.async.wait_group %0;" :: "n"(n) : "memory")

// m16n8k16 fp16 mma, fp32 accumulate.
// A frag (row-major m16k16): a0=(g,2t:2t+1) a1=(g+8,2t:2t+1) a2=(g,2t+8:+9) a3=(g+8,2t+8:+9)
// B frag (col-major k16n8): b0=(k=2t:2t+1, n=g) b1=(k=2t+8:+9, n=g)
// C: c0=(g,2t) c1=(g,2t+1) c2=(g+8,2t) c3=(g+8,2t+1)
__device__ __forceinline__ void mma_f16(float4& d, const uint4& a, const uint2& b) {
  asm volatile(
      "mma.sync.aligned.m16n8k16.row.col.f32.f16.f16.f32 "
      "{%0,%1,%2,%3}, {%4,%5,%6,%7}, {%8,%9}, {%0,%1,%2,%3};\n"
      : "+f"(d.x), "+f"(d.y), "+f"(d.z), "+f"(d.w)
      : "r"(a.x), "r"(a.y), "r"(a.z), "r"(a.w), "r"(b.x), "r"(b.y));
}

// ---------------------------------------------------------------------------
// Input permutes: fp32 row-major -> fp16 fragment-packed.
// A: [mb][kb(K/32)][mi(8)][ki(2)][lane(32)][uint4]  (m16k16 frags)
// B: [kb][nb(N/128)][ki(2)][ni(16)][lane(32)][uint2] (k16n8 frags)
// ---------------------------------------------------------------------------
__global__ void permute_A_kernel(const float* __restrict__ src,
                                 __half* __restrict__ dst, int M, int K) {
  int idx = blockIdx.x * blockDim.x + threadIdx.x;
  int l  = idx & 31;
  int fi = (idx >> 5) & 15;
  int blk = idx >> 9;
  int Kb = K >> 5;
  int kb = blk % Kb, mb = blk / Kb;
  if (mb >= (M >> 7)) return;
  int mi = fi >> 1, ki = fi & 1;
  int g = l >> 2, t = l & 3;
  size_t r = mb * 128 + mi * 16 + g;
  size_t c = kb * 32 + ki * 16 + 2 * t;
  uint4 v;
  v.x = f22h(src[r * K + c],       src[r * K + c + 1]);
  v.y = f22h(src[(r + 8) * K + c], src[(r + 8) * K + c + 1]);
  v.z = f22h(src[r * K + c + 8],   src[r * K + c + 9]);
  v.w = f22h(src[(r + 8) * K + c + 8], src[(r + 8) * K + c + 9]);
  ((uint4*)dst)[idx] = v;
}

__global__ void permute_B_kernel(const float* __restrict__ src,
                                 __half* __restrict__ dst, int K, int N) {
  int idx = blockIdx.x * blockDim.x + threadIdx.x;
  int l  = idx & 31;
  int fi = (idx >> 5) & 31;
  int blk = idx >> 10;
  int Nb = N >> 7;
  int nb = blk % Nb, kb = blk / Nb;
  if (kb >= (K >> 5)) return;
  int ki = fi >> 4, ni = fi & 15;
  int g = l >> 2, t = l & 3;
  size_t k = kb * 32 + ki * 16 + 2 * t;
  size_t n = nb * 128 + ni * 8 + g;
  uint2 v;
  v.x = f22h(src[k * N + n],       src[(k + 1) * N + n]);
  v.y = f22h(src[(k + 8) * N + n], src[(k + 9) * N + n]);
  ((uint2*)dst)[idx] = v;
}

// ---------------------------------------------------------------------------
// fp16 hand-mma GEMM: 128x128x64 block, 8 warps 2x4 (warp 64x32), 3-stage.
// mode 0: fp32 row-major store to Cv. mode 1: fused QKV packing epilogue
// (Q -> g_qA A-frags scaled 1/8; K1/K2/V -> g_kvp B-frag tiles).
// ---------------------------------------------------------------------------
#define TMM 128
#define TNN 128
#define TKK 64
#define ASTGH 8192
#define BSTGH 8192
#define GEMM_SMEM (3 * (ASTGH + BSTGH) * 2)   // 98,304 B
#define LDS 132

__global__ __launch_bounds__(256, 2) void gemm_tc(
    const __half* __restrict__ Apk, const __half* __restrict__ Bpk,
    void* __restrict__ Cv, __half* __restrict__ C2,
    int M, int N, int K, int mode) {
  extern __shared__ char smraw[];
  __half* Ash = (__half*)smraw;
  __half* Bsh = Ash + 3 * ASTGH;
  float* smg = (float*)smraw;
  const uint32_t sA = smem_u32(Ash);
  const uint32_t sB = smem_u32(Bsh);

  const int tid  = threadIdx.x;
  const int lane = tid & 31;
  const int warp = tid >> 5;
  const int wm   = warp & 1;
  const int wn   = warp >> 1;
  const int bm   = blockIdx.y * TMM;
  const int bn   = blockIdx.x * TNN;
  const int Kb   = K >> 5;
  const int Nb   = N >> 7;

#define G_ISSUE(k0, s)                                                          \
  {                                                                             \
    const __half* asrc = Apk + ((size_t)(bm >> 7) * Kb + ((k0) >> 5)) * 4096;   \
    const __half* b0src = Bpk + ((size_t)((k0) >> 5) * Nb + (bn >> 7)) * 4096;  \
    const __half* b1src = b0src + (size_t)Nb * 4096;                            \
    uint32_t aB = sA + (uint32_t)(s) * (ASTGH * 2);                             \
    uint32_t bB = sB + (uint32_t)(s) * (BSTGH * 2);                             \
    _Pragma("unroll") for (int j = 0; j < 4; j++)                               \
      CP_ASYNC16(aB + (uint32_t)(tid * 16 + j * 4096), asrc + tid * 8 + j * 2048); \
    _Pragma("unroll") for (int j = 0; j < 2; j++)                               \
      CP_ASYNC16(bB + (uint32_t)(tid * 16 + j * 4096), b0src + tid * 8 + j * 2048); \
    _Pragma("unroll") for (int j = 0; j < 2; j++)                               \
      CP_ASYNC16(bB + (uint32_t)(8192 + tid * 16 + j * 4096), b1src + tid * 8 + j * 2048); \
    CP_COMMIT();                                                                \
  }

  float4 acc[4][4];
#pragma unroll
  for (int i = 0; i < 4; i++)
#pragma unroll
    for (int j = 0; j < 4; j++) acc[i][j] = make_float4(0.f, 0.f, 0.f, 0.f);

  G_ISSUE(0, 0);
  G_ISSUE(TKK, 1);

  const int niter = K / TKK;
  for (int it = 0; it < niter; it++) {
    if (it == niter - 1) CP_WAIT(0); else CP_WAIT(1);
    __syncthreads();
    if (it + 2 < niter) G_ISSUE((it + 2) * TKK, (it + 2) % 3);

    const __half* As_ = Ash + (it % 3) * ASTGH;
    const __half* Bs_ = Bsh + (it % 3) * BSTGH;
#pragma unroll
    for (int q = 0; q < 4; q++) {
      const int kb2 = q >> 1, kiq = q & 1;
      uint4 a[4];
      uint2 b[4];
#pragma unroll
      for (int i = 0; i < 4; i++)
        a[i] = *(const uint4*)&As_[kb2 * 4096 + ((wm * 4 + i) * 2 + kiq) * 256 + lane * 8];
#pragma unroll
      for (int j = 0; j < 4; j++)
        b[j] = *(const uint2*)&Bs_[kb2 * 4096 + (kiq * 16 + wn * 4 + j) * 128 + lane * 4];
#pragma unroll
      for (int i = 0; i < 4; i++)
#pragma unroll
        for (int j = 0; j < 4; j++) mma_f16(acc[i][j], a[i], b[j]);
    }
  }

  // stage C tile (fp32) in smem
  __syncthreads();
  {
    const int g = lane >> 2, t = lane & 3;
#pragma unroll
    for (int i = 0; i < 4; i++)
#pragma unroll
      for (int j = 0; j < 4; j++) {
        int r0 = wm * 64 + i * 16 + g;
        int cc = wn * 32 + j * 8 + t * 2;
        *(float2*)&smg[r0 * LDS + cc] = make_float2(acc[i][j].x, acc[i][j].y);
        *(float2*)&smg[(r0 + 8) * LDS + cc] = make_float2(acc[i][j].z, acc[i][j].w);
      }
  }
  __syncthreads();

  if (mode == 0) {
    float* C = (float*)Cv;
#pragma unroll
    for (int i = 0; i < 16; i++) {
      int f = tid + i * 256;
      int r = f >> 5, c4 = (f & 31) * 4;
      float4 v = *(const float4*)&smg[r * LDS + c4];
      *(float4*)&C[(size_t)(bm + r) * N + bn + c4] = v;
    }
  } else {
    __half* Ch = (__half*)Cv;
    const int b    = bm >> 11;
    const int tok0 = bm & 2047;
    const int itq  = tok0 >> 7;
    const int jb0  = tok0 >> 6;
#pragma unroll
    for (int hc = 0; hc < 2; hc++) {
      const int gcol0 = bn + hc * 64;
      const int h  = gcol0 / 320;
      const int c5 = gcol0 % 320;
      const float* sbase = smg + hc * 64;
      if (c5 < 128) {
        // Q1/Q2 -> A-frag packed, scaled 1/8
        const int path = c5 >> 6;
        __half* qdst = Ch + (((size_t)(b * NH + h) * 16 + itq) * 2 + path) * 8192;
#pragma unroll
        for (int s = 0; s < 4; s++) {
          int f4 = tid + s * 256;
          int l2 = f4 & 31, kk = (f4 >> 5) & 3, wl = f4 >> 7;
          int gg = l2 >> 2, tp = l2 & 3;
          int r = wl * 16 + gg, c = kk * 16 + 2 * tp;
          uint4 v;
          v.x = f22h(sbase[r * LDS + c] * 0.125f,       sbase[r * LDS + c + 1] * 0.125f);
          v.y = f22h(sbase[(r + 8) * LDS + c] * 0.125f, sbase[(r + 8) * LDS + c + 1] * 0.125f);
          v.z = f22h(sbase[r * LDS + c + 8] * 0.125f,   sbase[r * LDS + c + 9] * 0.125f);
          v.w = f22h(sbase[(r + 8) * LDS + c + 8] * 0.125f, sbase[(r + 8) * LDS + c + 9] * 0.125f);
          *(uint4*)&qdst[(size_t)f4 * 8] = v;
        }
      } else if (c5 < 256) {
        // K1/K2 -> B-frag tiles (n = key, k = d)
        const int mat = (c5 - 128) >> 6;
#pragma unroll
        for (int jl = 0; jl < 2; jl++) {
          __half* t2 = C2 + ((size_t)(b * NH + h) * 32 + jb0 + jl) * 12288 + mat * 4096;
#pragma unroll
          for (int s = 0; s < 4; s++) {
            int f2 = tid + s * 256;
            int l2 = f2 & 31, kk = (f2 >> 5) & 3, nb = f2 >> 7;
            int gg = l2 >> 2, tp = l2 & 3;
            int row = jl * 64 + nb * 8 + gg, c = kk * 16 + 2 * tp;
            uint2 v;
            v.x = f22h(sbase[row * LDS + c],     sbase[row * LDS + c + 1]);
            v.y = f22h(sbase[row * LDS + c + 8], sbase[row * LDS + c + 9]);
            *(uint2*)&t2[((nb * 4 + kk) * 32 + l2) * 4] = v;
          }
        }
      } else {
        // V -> B-frag tiles (n = d, k = key)
#pragma unroll
        for (int jl = 0; jl < 2; jl++) {
          __half* t2 = C2 + ((size_t)(b * NH + h) * 32 + jb0 + jl) * 12288 + 8192;
#pragma unroll
          for (int s = 0; s < 4; s++) {
            int f2 = tid + s * 256;
            int l2 = f2 & 31, db = (f2 >> 5) & 7, kk = f2 >> 8;
            int gg = l2 >> 2, tp = l2 & 3;
            int row0 = jl * 64 + kk * 16 + 2 * tp, col = db * 8 + gg;
            uint2 v;
            v.x = f22h(sbase[row0 * LDS + col],       sbase[(row0 + 1) * LDS + col]);
            v.y = f22h(sbase[(row0 + 8) * LDS + col], sbase[(row0 + 9) * LDS + col]);
            *(uint2*)&t2[((kk * 8 + db) * 32 + l2) * 4] = v;
          }
        }
      }
    }
  }
}

// ---------------------------------------------------------------------------
// Path-parallel in-register fp16 differential attention. 512 threads.
// Warps 0-7 path1, 8-15 path2. acc->A-frag conversion is a pure fp16 pack.
// ---------------------------------------------------------------------------
#define KVTFH 12288  // halves per KV tile (24,576 B)
#define ATTN_SMEM (2 * KVTFH * 2)  // 49,152 B

__device__ __forceinline__ void attn_path(
    const uint4* __restrict__ qf, const __half* __restrict__ Kp,
    const __half* __restrict__ Vp, float4* __restrict__ O,
    float& slo, float& shi, int lane, int rowlo, int j0, bool needmask) {
  float4 s[8];
#pragma unroll
  for (int nb = 0; nb < 8; nb++) s[nb] = make_float4(0.f, 0.f, 0.f, 0.f);
#pragma unroll
  for (int kk = 0; kk < 4; kk++) {
    uint4 a = qf[kk];
#pragma unroll
    for (int nb = 0; nb < 8; nb++) {
      uint2 bb = *(const uint2*)&Kp[((nb * 4 + kk) * 32 + lane) * 4];
      mma_f16(s[nb], a, bb);
    }
  }
  const int t = lane & 3;
#pragma unroll
  for (int nb = 0; nb < 8; nb++) {
    float p0 = __expf(s[nb].x), p1 = __expf(s[nb].y);
    float p2 = __expf(s[nb].z), p3 = __expf(s[nb].w);
    if (needmask) {
      int jc = j0 + nb * 8 + 2 * t;
      int ihi = rowlo + 8;
      if (jc > rowlo)     p0 = 0.f;
      if (jc + 1 > rowlo) p1 = 0.f;
      if (jc > ihi)       p2 = 0.f;
      if (jc + 1 > ihi)   p3 = 0.f;
    }
    slo += p0 + p1;
    shi += p2 + p3;
    s[nb] = make_float4(p0, p1, p2, p3);
  }
  uint4 P[4];
#pragma unroll
  for (int kk = 0; kk < 4; kk++) {
    P[kk].x = f22h(s[2 * kk].x, s[2 * kk].y);
    P[kk].y = f22h(s[2 * kk].z, s[2 * kk].w);
    P[kk].z = f22h(s[2 * kk + 1].x, s[2 * kk + 1].y);
    P[kk].w = f22h(s[2 * kk + 1].z, s[2 * kk + 1].w);
  }
#pragma unroll
  for (int kk = 0; kk < 4; kk++) {
    uint4 a = P[kk];
#pragma unroll
    for (int db = 0; db < 8; db++) {
      uint2 bb = *(const uint2*)&Vp[((kk * 8 + db) * 32 + lane) * 4];
      mma_f16(O[db], a, bb);
    }
  }
}

__global__ __launch_bounds__(512) void attn_kernel(
    const float* __restrict__ lam_p, __half* __restrict__ attn_out) {
  extern __shared__ char smraw[];
  __half* smh = (__half*)smraw;
  float* smf = (float*)smraw;
  const uint32_t s0 = smem_u32(smraw);
  const int tid  = threadIdx.x;
  const int lane = tid & 31;
  const int warp = tid >> 5;
  const int path = warp >> 3;
  const int wl   = warp & 7;
  const int g    = lane >> 2;
  const int b    = blockIdx.z;
  const int h    = blockIdx.y;
  const int i0   = (int)(gridDim.x - 1 - blockIdx.x) * 128;  // heavy first
  const float lamc = fminf(fmaxf(lam_p[h], 0.0f), 1.0f);

  const __half* kvbase = g_kvp + (size_t)((b * NH + h) * 32) * KVTFH;

#define ATT_ISSUE_KV(jb, s)                                                    \
  {                                                                            \
    const __half* src = kvbase + (size_t)(jb) * KVTFH;                         \
    uint32_t dst = s0 + (uint32_t)(s) * (KVTFH * 2);                           \
    _Pragma("unroll") for (int i = 0; i < 3; i++)                              \
      CP_ASYNC16(dst + (uint32_t)(tid * 16 + i * 8192), src + tid * 8 + i * 4096); \
    CP_COMMIT();                                                               \
  }

  ATT_ISSUE_KV(0, 0);
  ATT_ISSUE_KV(1, 1);

  // Q fragments: coalesced LDG from packed g_qA
  uint4 qf[4];
  {
    const __half* gq = g_qA +
        (((size_t)(b * NH + h) * 16 + (i0 >> 7)) * 2 + path) * 8192 + wl * 1024;
#pragma unroll
    for (int kk = 0; kk < 4; kk++)
      qf[kk] = *(const uint4*)&gq[kk * 256 + lane * 8];
  }

  float4 O[8];
#pragma unroll
  for (int i = 0; i < 8; i++) O[i] = make_float4(0.f, 0.f, 0.f, 0.f);
  float slo = 0.f, shi = 0.f;
  const int rowlo = i0 + wl * 16 + g;

  const int ntiles = i0 / 64 + 2;
  for (int tt = 0; tt < ntiles; tt++) {
    if (tt == ntiles - 1) CP_WAIT(0); else CP_WAIT(1);
    __syncthreads();
    const int j0 = tt * 64;
    if (j0 <= i0 + wl * 16 + 15) {  // warp-uniform early-out
      const __half* kv = smh + (tt & 1) * KVTFH;
      const bool needmask = (j0 + 63 > i0 + wl * 16);
      attn_path(qf, kv + path * 4096, kv + 8192, O, slo, shi, lane, rowlo, j0, needmask);
    }
    __syncthreads();
    if (tt + 2 < ntiles) ATT_ISSUE_KV(tt + 2, tt & 1);
  }

  // quad-reduce row sums
  slo += __shfl_xor_sync(0xffffffffu, slo, 1);
  slo += __shfl_xor_sync(0xffffffffu, slo, 2);
  shi += __shfl_xor_sync(0xffffffffu, shi, 1);
  shi += __shfl_xor_sync(0xffffffffu, shi, 2);
  const float ilo = (path ? lamc : 1.0f) / slo;
  const float ihi = (path ? lamc : 1.0f) / shi;

  __syncthreads();  // all warps done reading KV smem before handoff reuse
  if (path == 1) {
#pragma unroll
    for (int db = 0; db < 8; db++) {
      float4 o;
      o.x = O[db].x * ilo; o.y = O[db].y * ilo;
      o.z = O[db].z * ihi; o.w = O[db].w * ihi;
      *(float4*)&smf[((wl * 8 + db) * 32 + lane) * 4] = o;
    }
  }
  __syncthreads();
  if (path == 0) {
    const int grow = b * NT + i0 + wl * 16;
    const int mb = grow >> 7;
    const int mi = (grow >> 4) & 7;
    float4 c[8];
#pragma unroll
    for (int db = 0; db < 8; db++) {
      float4 o2 = *(const float4*)&smf[((wl * 8 + db) * 32 + lane) * 4];
      c[db].x = O[db].x * ilo - o2.x;
      c[db].y = O[db].y * ilo - o2.y;
      c[db].z = O[db].z * ihi - o2.z;
      c[db].w = O[db].w * ihi - o2.w;
    }
#pragma unroll
    for (int kf = 0; kf < 4; kf++) {
      uint4 v;
      v.x = f22h(c[2 * kf].x, c[2 * kf].y);
      v.y = f22h(c[2 * kf].z, c[2 * kf].w);
      v.z = f22h(c[2 * kf + 1].x, c[2 * kf + 1].y);
      v.w = f22h(c[2 * kf + 1].z, c[2 * kf + 1].w);
      int gcol = h * 64 + kf * 16;
      int kb = gcol >> 5, ki = (gcol >> 4) & 1;
      size_t hidx = ((((size_t)(mb * 32 + kb) * 8 + mi) * 2 + ki) * 32 + lane) * 8;
      *(uint4*)&attn_out[hidx] = v;
    }
  }
}

// ---------------------------------------------------------------------------
extern "C" void kernel_launch(void* const* d_in, const int* in_sizes, int n_in,
                              void* d_out, int out_size) {
  const float* x    = (const float*)d_in[0];
  // d_in[1] = mask: exact causal additive mask; handled analytically.
  const float* Wqkv = (const float*)d_in[2];
  const float* Wout = (const float*)d_in[3];
  const float* lam  = (const float*)d_in[4];

  __half *qA_d, *attn_d, *x_d, *wq_d, *wo_d, *kvp_d;
  cudaGetSymbolAddress((void**)&qA_d, g_qA);
  cudaGetSymbolAddress((void**)&attn_d, g_attn);
  cudaGetSymbolAddress((void**)&x_d, g_x);
  cudaGetSymbolAddress((void**)&wq_d, g_wq);
  cudaGetSymbolAddress((void**)&wo_d, g_wo);
  cudaGetSymbolAddress((void**)&kvp_d, g_kvp);

  cudaFuncSetAttribute(gemm_tc, cudaFuncAttributeMaxDynamicSharedMemorySize, GEMM_SMEM);
  cudaFuncSetAttribute(attn_kernel, cudaFuncAttributeMaxDynamicSharedMemorySize, ATTN_SMEM);

  // 0) permute + fp16-round inputs into fragment-packed layouts.
  // permute_A threads handle 8 halves (uint4); permute_B threads handle 4 (uint2).
  permute_A_kernel<<<BTOT * NDM / 8 / 256, 256>>>(x, x_d, BTOT, NDM);
  permute_B_kernel<<<NDM * QKVN / 4 / 256, 256>>>(Wqkv, wq_d, NDM, QKVN);
  permute_B_kernel<<<NDM * NDM / 4 / 256, 256>>>(Wout, wo_d, NDM, NDM);

  // 1) qkv = x @ W_qkv  (fused epilogue: Q -> A-frags scaled, K/V -> packed tiles)
  {
    dim3 grid(QKVN / TNN, BTOT / TMM);  // (40, 32)
    gemm_tc<<<grid, 256, GEMM_SMEM>>>(x_d, wq_d, (void*)qA_d, kvp_d,
                                      BTOT, QKVN, NDM, 1);
  }

  // 2) differential attention (path-parallel, in-register fp16)
  {
    dim3 grid(NT / 128, NH, NBATCH);  // (16, 16, 2)
    attn_kernel<<<grid, 512, ATTN_SMEM>>>(lam, attn_d);
  }

  // 3) out = attn @ W_out (fp32 out)
  {
    dim3 grid(NDM / TNN, BTOT / TMM);  // (8, 32)
    gemm_tc<<<grid, 256, GEMM_SMEM>>>(attn_d, wo_d, d_out, nullptr,
                                      BTOT, NDM, NDM, 0);
  }
}